// round 1
// baseline (speedup 1.0000x reference)
#include <cuda_runtime.h>
#include <cstdint>

// ---------------------------------------------------------------------------
// GCNNet: An = D^-1/2 (A+I) D^-1/2 with A = (mean_bands(graph) != 0).
// For Gaussian graph inputs A is all-ones => An = (1/30) * J (rank-1).
// k1: per-batch density flag (honest) + column-sum of real  (bandwidth-bound)
// k2: collapsed per-batch MLP chain for dense batches        (compute)
// k3: full honest fallback for non-dense batches             (early-exit)
// ---------------------------------------------------------------------------

#define B_TOT   4096
#define BANDS   5
#define NN      30
#define IN_C    512
#define FF      128
#define CC      9
#define TB      16            // batches per k2 block

// scratch (device globals: allowed; no runtime allocation)
__device__ float4 g_rs4[B_TOT * (IN_C / 4)];   // per-batch column sums of real
__device__ int    g_flag[B_TOT];               // 1 = dense pattern (An rank-1)

// ---------------------------------------------------------------------------
// k1: one block per batch. Computes:
//   flag[b] = all off-diagonal entries of mean_bands(graph[b]) nonzero
//   rs[b,c] = sum_n real[b,n,c]
// ---------------------------------------------------------------------------
__global__ void __launch_bounds__(128) k1_flags_colsum(
    const float* __restrict__ real, const float* __restrict__ graph)
{
    int b = blockIdx.x;
    int tid = threadIdx.x;
    __shared__ int ok;
    if (tid == 0) ok = 1;
    __syncthreads();

    // density check over graph[b]
    const float* g = graph + (size_t)b * (BANDS * NN * NN);
    bool myok = true;
    #pragma unroll
    for (int it = 0; it < 8; it++) {
        int p = tid + it * 128;
        if (p < NN * NN) {
            int n = p / NN, m = p - n * NN;
            if (n != m) {
                float s5 = g[p] + g[900 + p] + g[1800 + p] + g[2700 + p] + g[3600 + p];
                float mean = s5 * 0.2f;
                if (mean == 0.0f) myok = false;
            }
        }
    }
    if (!myok) ok = 0;

    // column-sum of real[b] : [30,512] -> [512], vectorized float4
    const float4* r4 = (const float4*)(real + (size_t)b * NN * IN_C);
    int c4 = tid;             // 0..127, covers 512 floats
    float4 acc = make_float4(0.f, 0.f, 0.f, 0.f);
    #pragma unroll 6
    for (int n = 0; n < NN; n++) {
        float4 v = r4[n * (IN_C / 4) + c4];
        acc.x += v.x; acc.y += v.y; acc.z += v.z; acc.w += v.w;
    }
    g_rs4[b * (IN_C / 4) + c4] = acc;

    __syncthreads();
    if (tid == 0) g_flag[b] = ok;
}

// ---------------------------------------------------------------------------
// k2: dense path. block = 256 threads, TB=16 batches.
//   thread tid: f = tid&127, jh = tid>>7 covers 8 batches each.
//   h1 = relu(s * (colsum(real) @ W1) + b1)   (s = rsqrt(30)^2)
//   h2 = relu(30s * (h1 @ W2) + b2)
//   x  = relu(h2 . Wlin + blin)
//   out[c] = x * sum_n Wconv[c,n] + bconv[c]
// ---------------------------------------------------------------------------
__global__ void __launch_bounds__(256) k2_dense(
    const float* __restrict__ W1, const float* __restrict__ b1,
    const float* __restrict__ W2, const float* __restrict__ b2,
    const float* __restrict__ Wlin, const float* __restrict__ blin,
    const float* __restrict__ Wconv, const float* __restrict__ bconv,
    float* __restrict__ out)
{
    __shared__ float4 us4[TB * (IN_C / 4)];  // 32 KB: colsums (later reused for h2)
    __shared__ float4 h14[TB * (FF / 4)];    // 8 KB : h1
    __shared__ float  xs[TB];
    __shared__ float  wsum[CC];
    __shared__ int    flagS[TB];

    int tid = threadIdx.x;
    int b0  = blockIdx.x * TB;

    if (tid < CC) {
        float a = 0.f;
        #pragma unroll
        for (int n = 0; n < NN; n++) a += Wconv[tid * NN + n];
        wsum[tid] = a;
    }
    if (tid < TB) flagS[tid] = g_flag[b0 + tid];
    for (int i = tid; i < TB * (IN_C / 4); i += 256)
        us4[i] = g_rs4[b0 * (IN_C / 4) + i];
    __syncthreads();

    const int f  = tid & 127;
    const int jh = tid >> 7;                 // 0 or 1 (8 batches each)
    const float d  = rsqrtf(30.0f);
    const float s  = d * d;                  // An entry when dense
    const float r2 = 30.0f * s;              // row-sum of An when dense

    // ---- layer 1: acc[j] = colsum . W1[:,f]
    float acc[8];
    #pragma unroll
    for (int j = 0; j < 8; j++) acc[j] = 0.f;
    const float4* ub = us4 + jh * 8 * (IN_C / 4);
    for (int k4 = 0; k4 < IN_C / 4; k4++) {
        int k = k4 * 4;
        float w0 = W1[(k + 0) * FF + f];
        float w1 = W1[(k + 1) * FF + f];
        float w2 = W1[(k + 2) * FF + f];
        float w3 = W1[(k + 3) * FF + f];
        #pragma unroll
        for (int j = 0; j < 8; j++) {
            float4 u = ub[j * (IN_C / 4) + k4];
            acc[j] += u.x * w0 + u.y * w1 + u.z * w2 + u.w * w3;
        }
    }
    {
        float bb = b1[f];
        float* h1f = (float*)h14;
        #pragma unroll
        for (int j = 0; j < 8; j++)
            h1f[(jh * 8 + j) * FF + f] = fmaxf(s * acc[j] + bb, 0.0f);
    }
    __syncthreads();

    // ---- layer 2: acc[j] = h1 . W2[:,f]
    #pragma unroll
    for (int j = 0; j < 8; j++) acc[j] = 0.f;
    const float4* hb = h14 + jh * 8 * (FF / 4);
    for (int k4 = 0; k4 < FF / 4; k4++) {
        int k = k4 * 4;
        float w0 = W2[(k + 0) * FF + f];
        float w1 = W2[(k + 1) * FF + f];
        float w2 = W2[(k + 2) * FF + f];
        float w3 = W2[(k + 3) * FF + f];
        #pragma unroll
        for (int j = 0; j < 8; j++) {
            float4 u = hb[j * (FF / 4) + k4];
            acc[j] += u.x * w0 + u.y * w1 + u.z * w2 + u.w * w3;
        }
    }
    float* h2f = (float*)us4;                // reuse (us4 no longer needed)
    {
        float bb = b2[f];
        #pragma unroll
        for (int j = 0; j < 8; j++)
            h2f[(jh * 8 + j) * FF + f] = fmaxf(r2 * acc[j] + bb, 0.0f);
    }
    __syncthreads();

    // ---- x[j] = relu(h2 . Wlin + blin), 16 lanes per batch
    {
        int j = tid >> 4;                    // 0..15
        int l = tid & 15;
        float p = 0.f;
        #pragma unroll
        for (int ff = l; ff < FF; ff += 16) p += h2f[j * FF + ff] * Wlin[ff];
        p += __shfl_xor_sync(0xffffffff, p, 8);
        p += __shfl_xor_sync(0xffffffff, p, 4);
        p += __shfl_xor_sync(0xffffffff, p, 2);
        p += __shfl_xor_sync(0xffffffff, p, 1);
        if (l == 0) xs[j] = fmaxf(p + blin[0], 0.0f);
    }
    __syncthreads();

    // ---- out
    for (int idx = tid; idx < TB * CC; idx += 256) {
        int j = idx / CC, c = idx - j * CC;
        if (flagS[j])
            out[(size_t)(b0 + j) * CC + c] = xs[j] * wsum[c] + bconv[c];
    }
}

// ---------------------------------------------------------------------------
// k3: honest fallback for non-dense batches (early exit when flag set).
// One block (128 threads, thread = feature f) per batch.
// ---------------------------------------------------------------------------
__global__ void __launch_bounds__(128) k3_fallback(
    const float* __restrict__ real, const float* __restrict__ graph,
    const float* __restrict__ W1, const float* __restrict__ b1,
    const float* __restrict__ W2, const float* __restrict__ b2,
    const float* __restrict__ Wlin, const float* __restrict__ blin,
    const float* __restrict__ Wconv, const float* __restrict__ bconv,
    float* __restrict__ out)
{
    int b = blockIdx.x;
    if (g_flag[b]) return;

    __shared__ float An[NN * NN];
    __shared__ float dinv[NN];
    __shared__ float Ys[NN * FF];
    __shared__ float Hs[NN * FF];
    __shared__ float rrow[IN_C];
    __shared__ float xsb[NN];
    int tid = threadIdx.x;   // 128

    const float* g = graph + (size_t)b * (BANDS * NN * NN);
    for (int p = tid; p < NN * NN; p += 128) {
        int n = p / NN, m = p - n * NN;
        float s5 = g[p] + g[900 + p] + g[1800 + p] + g[2700 + p] + g[3600 + p];
        float mean = s5 * 0.2f;
        float a = (mean != 0.0f) ? 1.0f : 0.0f;
        if (n == m) a = 1.0f;
        An[p] = a;
    }
    __syncthreads();
    if (tid < NN) {
        float dg = 0.f;
        for (int m = 0; m < NN; m++) dg += An[tid * NN + m];
        dinv[tid] = (dg > 0.f) ? rsqrtf(dg) : 0.0f;
    }
    __syncthreads();
    for (int p = tid; p < NN * NN; p += 128) {
        int n = p / NN, m = p - n * NN;
        An[p] = dinv[n] * An[p] * dinv[m];
    }
    __syncthreads();

    // Y = real[b] @ W1
    const float* rb = real + (size_t)b * NN * IN_C;
    for (int n = 0; n < NN; n++) {
        for (int c = tid; c < IN_C; c += 128) rrow[c] = rb[n * IN_C + c];
        __syncthreads();
        float accv = 0.f;
        for (int c = 0; c < IN_C; c++) accv += rrow[c] * W1[c * FF + tid];
        Ys[n * FF + tid] = accv;
        __syncthreads();
    }
    // h1 = relu(An @ Y + b1)
    {
        float bb = b1[tid];
        for (int n = 0; n < NN; n++) {
            float accv = 0.f;
            for (int m = 0; m < NN; m++) accv += An[n * NN + m] * Ys[m * FF + tid];
            Hs[n * FF + tid] = fmaxf(accv + bb, 0.0f);
        }
    }
    __syncthreads();
    // T = h1 @ W2  (into Ys)
    for (int n = 0; n < NN; n++) {
        float accv = 0.f;
        for (int c = 0; c < FF; c++) accv += Hs[n * FF + c] * W2[c * FF + tid];
        Ys[n * FF + tid] = accv;
    }
    __syncthreads();
    // h2 = relu(An @ T + b2)
    {
        float bb = b2[tid];
        for (int n = 0; n < NN; n++) {
            float accv = 0.f;
            for (int m = 0; m < NN; m++) accv += An[n * NN + m] * Ys[m * FF + tid];
            Hs[n * FF + tid] = fmaxf(accv + bb, 0.0f);
        }
    }
    __syncthreads();
    if (tid < NN) {
        float accv = 0.f;
        for (int ff = 0; ff < FF; ff++) accv += Hs[tid * FF + ff] * Wlin[ff];
        xsb[tid] = fmaxf(accv + blin[0], 0.0f);
    }
    __syncthreads();
    if (tid < CC) {
        float accv = bconv[tid];
        for (int n = 0; n < NN; n++) accv += xsb[n] * Wconv[tid * NN + n];
        out[(size_t)b * CC + tid] = accv;
    }
}

// ---------------------------------------------------------------------------
extern "C" void kernel_launch(void* const* d_in, const int* in_sizes, int n_in,
                              void* d_out, int out_size)
{
    const float* real  = (const float*)d_in[0];
    // d_in[1] = imag: unused by the reference computation
    const float* graph = (const float*)d_in[2];
    const float* W1    = (const float*)d_in[3];
    const float* b1    = (const float*)d_in[4];
    const float* W2    = (const float*)d_in[5];
    const float* b2    = (const float*)d_in[6];
    const float* Wlin  = (const float*)d_in[7];
    const float* blin  = (const float*)d_in[8];
    const float* Wconv = (const float*)d_in[9];
    const float* bconv = (const float*)d_in[10];
    float* out = (float*)d_out;

    k1_flags_colsum<<<B_TOT, 128>>>(real, graph);
    k2_dense<<<B_TOT / TB, 256>>>(W1, b1, W2, b2, Wlin, blin, Wconv, bconv, out);
    k3_fallback<<<B_TOT, 128>>>(real, graph, W1, b1, W2, b2, Wlin, blin,
                                Wconv, bconv, out);
}

// round 2
// speedup vs baseline: 1.1626x; 1.1626x over previous
#include <cuda_runtime.h>
#include <cstdint>

// ---------------------------------------------------------------------------
// GCNNet: An = D^-1/2 (A+I) D^-1/2 with A = (mean_bands(graph) != 0).
// Dense pattern (measure-1 for Gaussian graph) => An = (1/30) * J (rank-1):
//   h1 rows identical = relu((1/30) colsum(real) @ W1 + b1)
//   h2 = relu(h1 @ W2 + b2)          (An row-sum = exactly 1.0)
//   x  = relu(h2 . Wlin + blin);  out[c] = x * sum_n Wconv[c,n] + bconv[c]
// k1: per-batch density flag (honest) + colsum(real)   [bandwidth-bound]
// k2: collapsed MLP chain, f32x2-packed FFMA2          [issue-bound]
// k3: full honest fallback for any non-dense batch     [early-exit]
// ---------------------------------------------------------------------------

#define B_TOT   4096
#define BANDS   5
#define NN      30
#define IN_C    512
#define FF      128
#define CC      9
#define TB      16            // batches per k2 block
#define S18     18            // padded k-row stride (floats) in smem

typedef unsigned long long u64t;

__device__ float4 g_rs4[B_TOT * (IN_C / 4)];   // per-batch column sums (b-major)
__device__ int    g_flag[B_TOT];               // 1 = dense pattern

// ---- f32x2 helpers --------------------------------------------------------
__device__ __forceinline__ u64t pk2(float lo, float hi) {
    u64t r; asm("mov.b64 %0,{%1,%2};" : "=l"(r) : "f"(lo), "f"(hi)); return r;
}
__device__ __forceinline__ void upk2(float& lo, float& hi, u64t v) {
    asm("mov.b64 {%0,%1},%2;" : "=f"(lo), "=f"(hi) : "l"(v));
}
__device__ __forceinline__ void fma2(u64t& d, u64t a, u64t b) {
    asm("fma.rn.f32x2 %0,%1,%2,%0;" : "+l"(d) : "l"(a), "l"(b));
}

// ---------------------------------------------------------------------------
// k1: one block per batch: density flag + colsum(real[b])  (b-major output)
// ---------------------------------------------------------------------------
__global__ void __launch_bounds__(128) k1_flags_colsum(
    const float* __restrict__ real, const float* __restrict__ graph)
{
    int b = blockIdx.x;
    int tid = threadIdx.x;
    __shared__ int ok;
    if (tid == 0) ok = 1;
    __syncthreads();

    const float* g = graph + (size_t)b * (BANDS * NN * NN);
    bool myok = true;
    #pragma unroll
    for (int it = 0; it < 8; it++) {
        int p = tid + it * 128;
        if (p < NN * NN) {
            int n = p / NN, m = p - n * NN;
            if (n != m) {
                float s5 = g[p] + g[900 + p] + g[1800 + p] + g[2700 + p] + g[3600 + p];
                if (s5 * 0.2f == 0.0f) myok = false;
            }
        }
    }
    if (!myok) ok = 0;

    const float4* r4 = (const float4*)(real + (size_t)b * NN * IN_C);
    int c4 = tid;
    float4 acc = make_float4(0.f, 0.f, 0.f, 0.f);
    #pragma unroll 6
    for (int n = 0; n < NN; n++) {
        float4 v = r4[n * (IN_C / 4) + c4];
        acc.x += v.x; acc.y += v.y; acc.z += v.z; acc.w += v.w;
    }
    g_rs4[b * (IN_C / 4) + c4] = acc;

    __syncthreads();
    if (tid == 0) g_flag[b] = ok;
}

// ---------------------------------------------------------------------------
// k2: dense path. 128 threads, TB=16 batches per block (grid 256).
// Thread (fg = tid&31, pg = tid>>5): features f = 4*fg..+3, batches 4*pg..+3
// (two f32x2 pairs). Warp == one pg; lane == fg.
// ---------------------------------------------------------------------------
__global__ void __launch_bounds__(128) k2_dense(
    const float* __restrict__ W1, const float* __restrict__ b1,
    const float* __restrict__ W2, const float* __restrict__ b2,
    const float* __restrict__ Wlin, const float* __restrict__ blin,
    const float* __restrict__ Wconv, const float* __restrict__ bconv,
    float* __restrict__ out)
{
    __shared__ float usT[IN_C * S18];   // 36.9 KB : colsums, k-major [k][b]
    __shared__ float h1T[FF * S18];     //  9.2 KB : h1, k-major [f][b]
    __shared__ float wsum[CC];
    __shared__ int   flagS[TB];

    int tid = threadIdx.x;
    int b0  = blockIdx.x * TB;

    if (tid < CC) {
        float a = 0.f;
        #pragma unroll
        for (int n = 0; n < NN; n++) a += Wconv[tid * NN + n];
        wsum[tid] = a;
    }
    if (tid < TB) flagS[tid] = g_flag[b0 + tid];

    // load colsums (coalesced) and transpose into k-major smem
    for (int i = tid; i < TB * (IN_C / 4); i += 128) {
        int b = i >> 7, k4 = i & 127;
        float4 v = g_rs4[(b0 + b) * (IN_C / 4) + k4];
        int k = k4 * 4;
        usT[(k + 0) * S18 + b] = v.x;
        usT[(k + 1) * S18 + b] = v.y;
        usT[(k + 2) * S18 + b] = v.z;
        usT[(k + 3) * S18 + b] = v.w;
    }
    __syncthreads();

    const int fg = tid & 31;
    const int pg = tid >> 5;
    const int f  = fg * 4;
    const float s1 = 1.0f / 30.0f;     // An entry (dense)

    u64t acc[2][4];
    #pragma unroll
    for (int p = 0; p < 2; p++)
        #pragma unroll
        for (int j = 0; j < 4; j++) acc[p][j] = 0ull;

    // ---- layer 1: acc[p][j] += u_pair[p] * W1[k][f+j]
    #pragma unroll 8
    for (int k = 0; k < IN_C; k++) {
        u64t uA = *(const u64t*)&usT[k * S18 + pg * 4];
        u64t uB = *(const u64t*)&usT[k * S18 + pg * 4 + 2];
        float4 w = *(const float4*)(W1 + k * FF + f);
        u64t w0 = pk2(w.x, w.x), w1 = pk2(w.y, w.y);
        u64t w2 = pk2(w.z, w.z), w3 = pk2(w.w, w.w);
        fma2(acc[0][0], uA, w0); fma2(acc[1][0], uB, w0);
        fma2(acc[0][1], uA, w1); fma2(acc[1][1], uB, w1);
        fma2(acc[0][2], uA, w2); fma2(acc[1][2], uB, w2);
        fma2(acc[0][3], uA, w3); fma2(acc[1][3], uB, w3);
    }
    #pragma unroll
    for (int j = 0; j < 4; j++) {
        float bb = b1[f + j];
        float c0, c1, c2, c3;
        upk2(c0, c1, acc[0][j]); upk2(c2, c3, acc[1][j]);
        float* row = &h1T[(f + j) * S18 + pg * 4];
        row[0] = fmaxf(fmaf(s1, c0, bb), 0.0f);
        row[1] = fmaxf(fmaf(s1, c1, bb), 0.0f);
        row[2] = fmaxf(fmaf(s1, c2, bb), 0.0f);
        row[3] = fmaxf(fmaf(s1, c3, bb), 0.0f);
    }
    __syncthreads();

    // ---- layer 2: same structure over h1T, K = 128
    #pragma unroll
    for (int p = 0; p < 2; p++)
        #pragma unroll
        for (int j = 0; j < 4; j++) acc[p][j] = 0ull;

    #pragma unroll 8
    for (int k = 0; k < FF; k++) {
        u64t uA = *(const u64t*)&h1T[k * S18 + pg * 4];
        u64t uB = *(const u64t*)&h1T[k * S18 + pg * 4 + 2];
        float4 w = *(const float4*)(W2 + k * FF + f);
        u64t w0 = pk2(w.x, w.x), w1 = pk2(w.y, w.y);
        u64t w2 = pk2(w.z, w.z), w3 = pk2(w.w, w.w);
        fma2(acc[0][0], uA, w0); fma2(acc[1][0], uB, w0);
        fma2(acc[0][1], uA, w1); fma2(acc[1][1], uB, w1);
        fma2(acc[0][2], uA, w2); fma2(acc[1][2], uB, w2);
        fma2(acc[0][3], uA, w3); fma2(acc[1][3], uB, w3);
    }

    // ---- h2 = relu(acc + b2) (An row-sum scale == 1), partial x-dot with Wlin
    float part[4] = {0.f, 0.f, 0.f, 0.f};
    #pragma unroll
    for (int j = 0; j < 4; j++) {
        float bb = b2[f + j];
        float wl = Wlin[f + j];
        float c0, c1, c2, c3;
        upk2(c0, c1, acc[0][j]); upk2(c2, c3, acc[1][j]);
        part[0] += fmaxf(c0 + bb, 0.0f) * wl;
        part[1] += fmaxf(c1 + bb, 0.0f) * wl;
        part[2] += fmaxf(c2 + bb, 0.0f) * wl;
        part[3] += fmaxf(c3 + bb, 0.0f) * wl;
    }
    // butterfly reduce over the warp's 32 fgroups (full FF=128 via 4 f each)
    #pragma unroll
    for (int off = 16; off > 0; off >>= 1) {
        #pragma unroll
        for (int c = 0; c < 4; c++)
            part[c] += __shfl_xor_sync(0xffffffffu, part[c], off);
    }
    float bl = blin[0];
    float x0 = fmaxf(part[0] + bl, 0.0f);
    float x1 = fmaxf(part[1] + bl, 0.0f);
    float x2 = fmaxf(part[2] + bl, 0.0f);
    float x3 = fmaxf(part[3] + bl, 0.0f);

    // ---- out: warp pg writes its 4 batches x 9 channels
    float xv[4] = {x0, x1, x2, x3};
    int lane = fg;
    {
        int bi = lane / CC, c = lane - bi * CC;     // lanes 0..31 -> first 32 of 36
        if (lane < 32) {                            // (always true; keeps intent)
            if (bi < 4 && flagS[pg * 4 + bi])
                out[(size_t)(b0 + pg * 4 + bi) * CC + c] = xv[bi] * wsum[c] + bconv[c];
        }
        if (lane < 4) {                             // remaining (b3, c=5..8)
            int c2 = 5 + lane;
            if (flagS[pg * 4 + 3])
                out[(size_t)(b0 + pg * 4 + 3) * CC + c2] = xv[3] * wsum[c2] + bconv[c2];
        }
    }
}

// ---------------------------------------------------------------------------
// k3: honest fallback for non-dense batches (early exit when flag set).
// ---------------------------------------------------------------------------
__global__ void __launch_bounds__(128) k3_fallback(
    const float* __restrict__ real, const float* __restrict__ graph,
    const float* __restrict__ W1, const float* __restrict__ b1,
    const float* __restrict__ W2, const float* __restrict__ b2,
    const float* __restrict__ Wlin, const float* __restrict__ blin,
    const float* __restrict__ Wconv, const float* __restrict__ bconv,
    float* __restrict__ out)
{
    int b = blockIdx.x;
    if (g_flag[b]) return;

    __shared__ float An[NN * NN];
    __shared__ float dinv[NN];
    __shared__ float Ys[NN * FF];
    __shared__ float Hs[NN * FF];
    __shared__ float rrow[IN_C];
    __shared__ float xsb[NN];
    int tid = threadIdx.x;

    const float* g = graph + (size_t)b * (BANDS * NN * NN);
    for (int p = tid; p < NN * NN; p += 128) {
        int n = p / NN, m = p - n * NN;
        float s5 = g[p] + g[900 + p] + g[1800 + p] + g[2700 + p] + g[3600 + p];
        float a = (s5 * 0.2f != 0.0f) ? 1.0f : 0.0f;
        if (n == m) a = 1.0f;
        An[p] = a;
    }
    __syncthreads();
    if (tid < NN) {
        float dg = 0.f;
        for (int m = 0; m < NN; m++) dg += An[tid * NN + m];
        dinv[tid] = (dg > 0.f) ? rsqrtf(dg) : 0.0f;
    }
    __syncthreads();
    for (int p = tid; p < NN * NN; p += 128) {
        int n = p / NN, m = p - n * NN;
        An[p] = dinv[n] * An[p] * dinv[m];
    }
    __syncthreads();

    const float* rb = real + (size_t)b * NN * IN_C;
    for (int n = 0; n < NN; n++) {
        for (int c = tid; c < IN_C; c += 128) rrow[c] = rb[n * IN_C + c];
        __syncthreads();
        float accv = 0.f;
        for (int c = 0; c < IN_C; c++) accv += rrow[c] * W1[c * FF + tid];
        Ys[n * FF + tid] = accv;
        __syncthreads();
    }
    {
        float bb = b1[tid];
        for (int n = 0; n < NN; n++) {
            float accv = 0.f;
            for (int m = 0; m < NN; m++) accv += An[n * NN + m] * Ys[m * FF + tid];
            Hs[n * FF + tid] = fmaxf(accv + bb, 0.0f);
        }
    }
    __syncthreads();
    for (int n = 0; n < NN; n++) {
        float accv = 0.f;
        for (int c = 0; c < FF; c++) accv += Hs[n * FF + c] * W2[c * FF + tid];
        Ys[n * FF + tid] = accv;
    }
    __syncthreads();
    {
        float bb = b2[tid];
        for (int n = 0; n < NN; n++) {
            float accv = 0.f;
            for (int m = 0; m < NN; m++) accv += An[n * NN + m] * Ys[m * FF + tid];
            Hs[n * FF + tid] = fmaxf(accv + bb, 0.0f);
        }
    }
    __syncthreads();
    if (tid < NN) {
        float accv = 0.f;
        for (int ff = 0; ff < FF; ff++) accv += Hs[tid * FF + ff] * Wlin[ff];
        xsb[tid] = fmaxf(accv + blin[0], 0.0f);
    }
    __syncthreads();
    if (tid < CC) {
        float accv = bconv[tid];
        for (int n = 0; n < NN; n++) accv += xsb[n] * Wconv[tid * NN + n];
        out[(size_t)b * CC + tid] = accv;
    }
}

// ---------------------------------------------------------------------------
extern "C" void kernel_launch(void* const* d_in, const int* in_sizes, int n_in,
                              void* d_out, int out_size)
{
    const float* real  = (const float*)d_in[0];
    const float* graph = (const float*)d_in[2];
    const float* W1    = (const float*)d_in[3];
    const float* b1    = (const float*)d_in[4];
    const float* W2    = (const float*)d_in[5];
    const float* b2    = (const float*)d_in[6];
    const float* Wlin  = (const float*)d_in[7];
    const float* blin  = (const float*)d_in[8];
    const float* Wconv = (const float*)d_in[9];
    const float* bconv = (const float*)d_in[10];
    float* out = (float*)d_out;

    k1_flags_colsum<<<B_TOT, 128>>>(real, graph);
    k2_dense<<<B_TOT / TB, 128>>>(W1, b1, W2, b2, Wlin, blin, Wconv, bconv, out);
    k3_fallback<<<B_TOT, 128>>>(real, graph, W1, b1, W2, b2, Wlin, blin,
                                Wconv, bconv, out);
}

// round 3
// speedup vs baseline: 1.2834x; 1.1040x over previous
#include <cuda_runtime.h>
#include <cstdint>

// ---------------------------------------------------------------------------
// GCNNet: An = D^-1/2 (A+I) D^-1/2 with A = (mean_bands(graph) != 0).
// Dense pattern (measure-1 for Gaussian graph) => An = (1/30) * J (rank-1):
//   h1 rows identical = relu((1/30) colsum(real) @ W1 + b1)
//   h2 = relu(h1 @ W2 + b2)                (An row-sum = exactly 1.0)
//   x  = relu(h2 . Wlin + blin);  out[c] = x * sum_n Wconv[c,n] + bconv[c]
// k1: per-batch density flag (honest) + colsum(real)   [bandwidth-bound]
// k2: collapsed MLP (FFMA2, K split across warps) + honest fallback fused
// ---------------------------------------------------------------------------

#define B_TOT   4096
#define BANDS   5
#define NN      30
#define IN_C    512
#define FF      128
#define CC      9
#define TB      16            // batches per k2 block
#define S18     18            // padded batch stride (floats) in k-major smem

typedef unsigned long long u64t;

__device__ float4 g_rs4[B_TOT * (IN_C / 4)];   // per-batch column sums (b-major)
__device__ int    g_flag[B_TOT];               // 1 = dense pattern

// ---- f32x2 helpers --------------------------------------------------------
__device__ __forceinline__ u64t pk2(float lo, float hi) {
    u64t r; asm("mov.b64 %0,{%1,%2};" : "=l"(r) : "f"(lo), "f"(hi)); return r;
}
__device__ __forceinline__ void upk2(float& lo, float& hi, u64t v) {
    asm("mov.b64 {%0,%1},%2;" : "=f"(lo), "=f"(hi) : "l"(v));
}
__device__ __forceinline__ void fma2(u64t& d, u64t a, u64t b) {
    asm("fma.rn.f32x2 %0,%1,%2,%0;" : "+l"(d) : "l"(a), "l"(b));
}

// ---------------------------------------------------------------------------
// k1: one block per batch: density flag (float4 graph loads) + colsum(real)
// ---------------------------------------------------------------------------
__global__ void __launch_bounds__(128) k1_flags_colsum(
    const float* __restrict__ real, const float* __restrict__ graph)
{
    int b = blockIdx.x;
    int tid = threadIdx.x;
    __shared__ int ok;
    if (tid == 0) ok = 1;
    __syncthreads();

    // graph[b]: 5 bands x 900 floats = 5 x 225 float4 (16B-aligned per band)
    const float4* g4 = (const float4*)(graph + (size_t)b * (BANDS * NN * NN));
    bool myok = true;
    #pragma unroll
    for (int it = 0; it < 2; it++) {
        int idx = tid + it * 128;
        if (idx < 225) {
            float4 a = g4[idx];
            float4 c1 = g4[225 + idx];
            float4 c2 = g4[450 + idx];
            float4 c3 = g4[675 + idx];
            float4 c4 = g4[900 + idx];
            float s[4];
            s[0] = a.x + c1.x + c2.x + c3.x + c4.x;
            s[1] = a.y + c1.y + c2.y + c3.y + c4.y;
            s[2] = a.z + c1.z + c2.z + c3.z + c4.z;
            s[3] = a.w + c1.w + c2.w + c3.w + c4.w;
            #pragma unroll
            for (int j = 0; j < 4; j++) {
                int p = idx * 4 + j;
                int n = p / NN, m = p - n * NN;
                if (n != m && s[j] * 0.2f == 0.0f) myok = false;
            }
        }
    }
    if (!myok) ok = 0;

    // colsum of real[b] : [30,512] -> [512]
    const float4* r4 = (const float4*)(real + (size_t)b * NN * IN_C);
    int c4i = tid;
    float4 acc = make_float4(0.f, 0.f, 0.f, 0.f);
    #pragma unroll 10
    for (int n = 0; n < NN; n++) {
        float4 v = r4[n * (IN_C / 4) + c4i];
        acc.x += v.x; acc.y += v.y; acc.z += v.z; acc.w += v.w;
    }
    g_rs4[b * (IN_C / 4) + c4i] = acc;

    __syncthreads();
    if (tid == 0) g_flag[b] = ok;
}

// ---------------------------------------------------------------------------
// honest fallback for a single non-dense batch; whole block (256 thr) runs it.
// smemA is reused (>= 36736 bytes).
// ---------------------------------------------------------------------------
__device__ void fallback_batch(
    int b, char* smemA, int tid,
    const float* __restrict__ real, const float* __restrict__ graph,
    const float* __restrict__ W1, const float* __restrict__ b1,
    const float* __restrict__ W2, const float* __restrict__ b2,
    const float* __restrict__ Wlin, const float* __restrict__ blin,
    const float* __restrict__ Wconv, const float* __restrict__ bconv,
    float* __restrict__ out)
{
    float* An   = (float*)smemA;        // 900
    float* dinv = An + 900;             // 30 (pad to 960)
    float* Ys   = An + 960;             // 3840
    float* Hs   = Ys + 3840;            // 3840
    float* rrow = Hs + 3840;            // 512
    float* xsb  = rrow + 512;           // 30

    const float* g = graph + (size_t)b * (BANDS * NN * NN);
    for (int p = tid; p < NN * NN; p += 256) {
        int n = p / NN, m = p - n * NN;
        float s5 = g[p] + g[900 + p] + g[1800 + p] + g[2700 + p] + g[3600 + p];
        float a = (s5 * 0.2f != 0.0f) ? 1.0f : 0.0f;
        if (n == m) a = 1.0f;
        An[p] = a;
    }
    __syncthreads();
    if (tid < NN) {
        float dg = 0.f;
        for (int m = 0; m < NN; m++) dg += An[tid * NN + m];
        dinv[tid] = (dg > 0.f) ? rsqrtf(dg) : 0.0f;
    }
    __syncthreads();
    for (int p = tid; p < NN * NN; p += 256) {
        int n = p / NN, m = p - n * NN;
        An[p] = dinv[n] * An[p] * dinv[m];
    }
    __syncthreads();

    const float* rb = real + (size_t)b * NN * IN_C;
    for (int n = 0; n < NN; n++) {
        for (int c = tid; c < IN_C; c += 256) rrow[c] = rb[n * IN_C + c];
        __syncthreads();
        if (tid < FF) {
            float accv = 0.f;
            for (int c = 0; c < IN_C; c++) accv += rrow[c] * W1[c * FF + tid];
            Ys[n * FF + tid] = accv;
        }
        __syncthreads();
    }
    if (tid < FF) {
        float bb = b1[tid];
        for (int n = 0; n < NN; n++) {
            float accv = 0.f;
            for (int m = 0; m < NN; m++) accv += An[n * NN + m] * Ys[m * FF + tid];
            Hs[n * FF + tid] = fmaxf(accv + bb, 0.0f);
        }
    }
    __syncthreads();
    if (tid < FF) {
        for (int n = 0; n < NN; n++) {
            float accv = 0.f;
            for (int c = 0; c < FF; c++) accv += Hs[n * FF + c] * W2[c * FF + tid];
            Ys[n * FF + tid] = accv;
        }
    }
    __syncthreads();
    if (tid < FF) {
        float bb = b2[tid];
        for (int n = 0; n < NN; n++) {
            float accv = 0.f;
            for (int m = 0; m < NN; m++) accv += An[n * NN + m] * Ys[m * FF + tid];
            Hs[n * FF + tid] = fmaxf(accv + bb, 0.0f);
        }
    }
    __syncthreads();
    if (tid < NN) {
        float accv = 0.f;
        for (int ff = 0; ff < FF; ff++) accv += Hs[tid * FF + ff] * Wlin[ff];
        xsb[tid] = fmaxf(accv + blin[0], 0.0f);
    }
    __syncthreads();
    if (tid < CC) {
        float accv = bconv[tid];
        for (int n = 0; n < NN; n++) accv += xsb[n] * Wconv[tid * NN + n];
        out[(size_t)b * CC + tid] = accv;
    }
    __syncthreads();
}

// ---------------------------------------------------------------------------
// k2: dense path, 256 threads, TB=16 batches/block, grid 256.
// Warp w: kh = w>>1 (k-quarter), bh = w&1 (batch octet). Lane fg: f=4*fg..+3.
// Per-thread accumulators: 4 batch-pairs x 4 features (16 x f32x2).
// Cross-warp K-reduction through smem (aliases usT).
// ---------------------------------------------------------------------------
__global__ void __launch_bounds__(256) k2_dense(
    const float* __restrict__ real, const float* __restrict__ graph,
    const float* __restrict__ W1, const float* __restrict__ b1,
    const float* __restrict__ W2, const float* __restrict__ b2,
    const float* __restrict__ Wlin, const float* __restrict__ blin,
    const float* __restrict__ Wconv, const float* __restrict__ bconv,
    float* __restrict__ out)
{
    __shared__ __align__(16) char smemA[IN_C * S18 * 4];  // 36864B: usT | red | fallback
    __shared__ __align__(16) float h1T[FF * S18];         // 9216B
    __shared__ float wsum[CC];
    __shared__ float xs[TB];
    __shared__ float xp[8][8];     // [warp][bl]
    __shared__ int   flagS[TB];

    float* usT = (float*)smemA;            // [k][b], stride S18
    float* red = (float*)smemA;            // [kh][bh*1024 + bl*128 + f] (aliased)

    int tid = threadIdx.x;
    int b0  = blockIdx.x * TB;
    const int w    = tid >> 5;
    const int lane = tid & 31;
    const int kh   = w >> 1;               // 0..3
    const int bh   = w & 1;                // 0..1
    const int f4   = lane * 4;

    if (tid < CC) {
        float a = 0.f;
        #pragma unroll
        for (int n = 0; n < NN; n++) a += Wconv[tid * NN + n];
        wsum[tid] = a;
    }
    if (tid < TB) flagS[tid] = g_flag[b0 + tid];

    // load colsums (coalesced) and transpose into k-major usT
    for (int i = tid; i < TB * (IN_C / 4); i += 256) {
        int b = i >> 7, k4i = i & 127;
        float4 v = g_rs4[(b0 + b) * (IN_C / 4) + k4i];
        int k = k4i * 4;
        usT[(k + 0) * S18 + b] = v.x;
        usT[(k + 1) * S18 + b] = v.y;
        usT[(k + 2) * S18 + b] = v.z;
        usT[(k + 3) * S18 + b] = v.w;
    }
    __syncthreads();

    u64t acc[4][4];   // [pair p -> batches bh*8+2p,+1][feature j]
    #pragma unroll
    for (int p = 0; p < 4; p++)
        #pragma unroll
        for (int j = 0; j < 4; j++) acc[p][j] = 0ull;

    // ---- layer 1 partial: k in [kh*128, kh*128+128)
    {
        const int kbeg = kh * 128;
        #pragma unroll 4
        for (int ki = 0; ki < 128; ki++) {
            int k = kbeg + ki;
            const float* ub = &usT[k * S18 + bh * 8];
            u64t u0 = *(const u64t*)(ub + 0);
            u64t u1 = *(const u64t*)(ub + 2);
            u64t u2 = *(const u64t*)(ub + 4);
            u64t u3 = *(const u64t*)(ub + 6);
            float4 wv = *(const float4*)(W1 + k * FF + f4);
            u64t w0 = pk2(wv.x, wv.x), w1 = pk2(wv.y, wv.y);
            u64t w2 = pk2(wv.z, wv.z), w3 = pk2(wv.w, wv.w);
            fma2(acc[0][0], u0, w0); fma2(acc[1][0], u1, w0);
            fma2(acc[2][0], u2, w0); fma2(acc[3][0], u3, w0);
            fma2(acc[0][1], u0, w1); fma2(acc[1][1], u1, w1);
            fma2(acc[2][1], u2, w1); fma2(acc[3][1], u3, w1);
            fma2(acc[0][2], u0, w2); fma2(acc[1][2], u1, w2);
            fma2(acc[2][2], u2, w2); fma2(acc[3][2], u3, w2);
            fma2(acc[0][3], u0, w3); fma2(acc[1][3], u1, w3);
            fma2(acc[2][3], u2, w3); fma2(acc[3][3], u3, w3);
        }
    }
    __syncthreads();   // all reads of usT done before red overwrites it
    #pragma unroll
    for (int p = 0; p < 4; p++)
        #pragma unroll
        for (int j = 0; j < 4; j++) {
            float lo, hi;
            upk2(lo, hi, acc[p][j]);
            red[kh * 2048 + bh * 1024 + (2 * p) * 128 + f4 + j]     = lo;
            red[kh * 2048 + bh * 1024 + (2 * p + 1) * 128 + f4 + j] = hi;
        }
    __syncthreads();

    // ---- reduce over kh -> h1T[f][b]   (thread t: f=t&127, octet t>>7)
    {
        const float s1 = 1.0f / 30.0f;
        int fr  = tid & 127;
        int bh2 = tid >> 7;
        float bb = b1[fr];
        #pragma unroll
        for (int bl = 0; bl < 8; bl++) {
            int o = bh2 * 1024 + bl * 128 + fr;
            float s = red[o] + red[2048 + o] + red[4096 + o] + red[6144 + o];
            h1T[fr * S18 + bh2 * 8 + bl] = fmaxf(fmaf(s1, s, bb), 0.0f);
        }
    }
    __syncthreads();

    // ---- layer 2 partial: k in [kh*32, kh*32+32)
    #pragma unroll
    for (int p = 0; p < 4; p++)
        #pragma unroll
        for (int j = 0; j < 4; j++) acc[p][j] = 0ull;
    {
        const int kbeg = kh * 32;
        #pragma unroll 4
        for (int ki = 0; ki < 32; ki++) {
            int k = kbeg + ki;
            const float* ub = &h1T[k * S18 + bh * 8];
            u64t u0 = *(const u64t*)(ub + 0);
            u64t u1 = *(const u64t*)(ub + 2);
            u64t u2 = *(const u64t*)(ub + 4);
            u64t u3 = *(const u64t*)(ub + 6);
            float4 wv = *(const float4*)(W2 + k * FF + f4);
            u64t w0 = pk2(wv.x, wv.x), w1 = pk2(wv.y, wv.y);
            u64t w2 = pk2(wv.z, wv.z), w3 = pk2(wv.w, wv.w);
            fma2(acc[0][0], u0, w0); fma2(acc[1][0], u1, w0);
            fma2(acc[2][0], u2, w0); fma2(acc[3][0], u3, w0);
            fma2(acc[0][1], u0, w1); fma2(acc[1][1], u1, w1);
            fma2(acc[2][1], u2, w1); fma2(acc[3][1], u3, w1);
            fma2(acc[0][2], u0, w2); fma2(acc[1][2], u1, w2);
            fma2(acc[2][2], u2, w2); fma2(acc[3][2], u3, w2);
            fma2(acc[0][3], u0, w3); fma2(acc[1][3], u1, w3);
            fma2(acc[2][3], u2, w3); fma2(acc[3][3], u3, w3);
        }
    }
    __syncthreads();   // h1T reads done; red reuse is fine (same region as usT)
    #pragma unroll
    for (int p = 0; p < 4; p++)
        #pragma unroll
        for (int j = 0; j < 4; j++) {
            float lo, hi;
            upk2(lo, hi, acc[p][j]);
            red[kh * 2048 + bh * 1024 + (2 * p) * 128 + f4 + j]     = lo;
            red[kh * 2048 + bh * 1024 + (2 * p + 1) * 128 + f4 + j] = hi;
        }
    __syncthreads();

    // ---- reduce, h2 = relu(. + b2), partial x = h2 . Wlin
    {
        int fr  = tid & 127;
        int bh2 = tid >> 7;
        float bb = b2[fr];
        float wl = Wlin[fr];
        float part[8];
        #pragma unroll
        for (int bl = 0; bl < 8; bl++) {
            int o = bh2 * 1024 + bl * 128 + fr;
            float s = red[o] + red[2048 + o] + red[4096 + o] + red[6144 + o];
            part[bl] = fmaxf(s + bb, 0.0f) * wl;
        }
        #pragma unroll
        for (int off = 16; off > 0; off >>= 1)
            #pragma unroll
            for (int bl = 0; bl < 8; bl++)
                part[bl] += __shfl_xor_sync(0xffffffffu, part[bl], off);
        if (lane == 0) {
            #pragma unroll
            for (int bl = 0; bl < 8; bl++) xp[w][bl] = part[bl];
        }
    }
    __syncthreads();
    if (tid < TB) {
        int bh2 = tid >> 3, bl = tid & 7;
        float s = xp[bh2 * 4 + 0][bl] + xp[bh2 * 4 + 1][bl]
                + xp[bh2 * 4 + 2][bl] + xp[bh2 * 4 + 3][bl];
        xs[tid] = fmaxf(s + blin[0], 0.0f);
    }
    __syncthreads();

    if (tid < TB * CC) {
        int b = tid / CC, c = tid - b * CC;
        if (flagS[b])
            out[(size_t)(b0 + b) * CC + c] = xs[b] * wsum[c] + bconv[c];
    }

    // ---- honest fallback for any non-dense batch (uniform branch)
    __syncthreads();
    for (int fb = 0; fb < TB; fb++) {
        if (!flagS[fb]) {
            fallback_batch(b0 + fb, smemA, tid, real, graph, W1, b1, W2, b2,
                           Wlin, blin, Wconv, bconv, out);
        }
    }
}

// ---------------------------------------------------------------------------
extern "C" void kernel_launch(void* const* d_in, const int* in_sizes, int n_in,
                              void* d_out, int out_size)
{
    const float* real  = (const float*)d_in[0];
    const float* graph = (const float*)d_in[2];
    const float* W1    = (const float*)d_in[3];
    const float* b1    = (const float*)d_in[4];
    const float* W2    = (const float*)d_in[5];
    const float* b2    = (const float*)d_in[6];
    const float* Wlin  = (const float*)d_in[7];
    const float* blin  = (const float*)d_in[8];
    const float* Wconv = (const float*)d_in[9];
    const float* bconv = (const float*)d_in[10];
    float* out = (float*)d_out;

    k1_flags_colsum<<<B_TOT, 128>>>(real, graph);
    k2_dense<<<B_TOT / TB, 256>>>(real, graph, W1, b1, W2, b2, Wlin, blin,
                                  Wconv, bconv, out);
}

// round 4
// speedup vs baseline: 1.3648x; 1.0634x over previous
#include <cuda_runtime.h>
#include <cstdint>

// ---------------------------------------------------------------------------
// GCNNet fused single-kernel implementation.
// An = D^-1/2 (A+I) D^-1/2, A = (mean_bands(graph) != 0). Dense pattern
// (measure-1 for Gaussian graph) => An = (1/30)*J (rank-1):
//   h1 = relu((1/30) colsum(real) @ W1 + b1)      (all rows identical)
//   h2 = relu(h1 @ W2 + b2)                       (An row-sums == 1)
//   x  = relu(h2 . Wlin + blin); out[c] = x * rowsum(Wconv[c]) + bconv[c]
// Phase A: per-block flags + colsums (DRAM-bound, overlaps other blocks' B)
// Phase B: FFMA2 MLP, K split across 8 warps; honest per-batch fallback.
// ---------------------------------------------------------------------------

#define B_TOT   4096
#define BANDS   5
#define NN      30
#define IN_C    512
#define FF      128
#define CC      9
#define TB      8             // batches per block
#define SB      10            // padded batch stride (floats) in k-major smem

typedef unsigned long long u64t;

// ---- f32x2 helpers --------------------------------------------------------
__device__ __forceinline__ u64t pk2(float lo, float hi) {
    u64t r; asm("mov.b64 %0,{%1,%2};" : "=l"(r) : "f"(lo), "f"(hi)); return r;
}
__device__ __forceinline__ void upk2(float& lo, float& hi, u64t v) {
    asm("mov.b64 {%0,%1},%2;" : "=f"(lo), "=f"(hi) : "l"(v));
}
__device__ __forceinline__ void fma2(u64t& d, u64t a, u64t b) {
    asm("fma.rn.f32x2 %0,%1,%2,%0;" : "+l"(d) : "l"(a), "l"(b));
}

// ---------------------------------------------------------------------------
// honest fallback for one non-dense batch; whole block (256 thr), smem 'buf'
// (>= 36728 bytes) is reused.
// ---------------------------------------------------------------------------
__device__ void fallback_batch(
    int b, char* buf, int tid,
    const float* __restrict__ real, const float* __restrict__ graph,
    const float* __restrict__ W1, const float* __restrict__ b1,
    const float* __restrict__ W2, const float* __restrict__ b2,
    const float* __restrict__ Wlin, const float* __restrict__ blin,
    const float* __restrict__ Wconv, const float* __restrict__ bconv,
    float* __restrict__ out)
{
    float* An   = (float*)buf;          // 900 (pad to 960 incl. dinv)
    float* dinv = An + 900;             // 30
    float* Ys   = An + 960;             // 3840
    float* Hs   = Ys + 3840;            // 3840
    float* rrow = Hs + 3840;            // 512
    float* xsb  = rrow + 512;           // 30     total 9182 floats = 36728 B

    const float* g = graph + (size_t)b * (BANDS * NN * NN);
    for (int p = tid; p < NN * NN; p += 256) {
        int n = p / NN, m = p - n * NN;
        float s5 = g[p] + g[900 + p] + g[1800 + p] + g[2700 + p] + g[3600 + p];
        float a = (s5 * 0.2f != 0.0f) ? 1.0f : 0.0f;
        if (n == m) a = 1.0f;
        An[p] = a;
    }
    __syncthreads();
    if (tid < NN) {
        float dg = 0.f;
        for (int m = 0; m < NN; m++) dg += An[tid * NN + m];
        dinv[tid] = (dg > 0.f) ? rsqrtf(dg) : 0.0f;
    }
    __syncthreads();
    for (int p = tid; p < NN * NN; p += 256) {
        int n = p / NN, m = p - n * NN;
        An[p] = dinv[n] * An[p] * dinv[m];
    }
    __syncthreads();

    const float* rb = real + (size_t)b * NN * IN_C;
    for (int n = 0; n < NN; n++) {
        for (int c = tid; c < IN_C; c += 256) rrow[c] = rb[n * IN_C + c];
        __syncthreads();
        if (tid < FF) {
            float accv = 0.f;
            for (int c = 0; c < IN_C; c++) accv += rrow[c] * W1[c * FF + tid];
            Ys[n * FF + tid] = accv;
        }
        __syncthreads();
    }
    if (tid < FF) {
        float bb = b1[tid];
        for (int n = 0; n < NN; n++) {
            float accv = 0.f;
            for (int m = 0; m < NN; m++) accv += An[n * NN + m] * Ys[m * FF + tid];
            Hs[n * FF + tid] = fmaxf(accv + bb, 0.0f);
        }
    }
    __syncthreads();
    if (tid < FF) {
        for (int n = 0; n < NN; n++) {
            float accv = 0.f;
            for (int c = 0; c < FF; c++) accv += Hs[n * FF + c] * W2[c * FF + tid];
            Ys[n * FF + tid] = accv;
        }
    }
    __syncthreads();
    if (tid < FF) {
        float bb = b2[tid];
        for (int n = 0; n < NN; n++) {
            float accv = 0.f;
            for (int m = 0; m < NN; m++) accv += An[n * NN + m] * Ys[m * FF + tid];
            Hs[n * FF + tid] = fmaxf(accv + bb, 0.0f);
        }
    }
    __syncthreads();
    if (tid < NN) {
        float accv = 0.f;
        for (int ff = 0; ff < FF; ff++) accv += Hs[tid * FF + ff] * Wlin[ff];
        xsb[tid] = fmaxf(accv + blin[0], 0.0f);
    }
    __syncthreads();
    if (tid < CC) {
        float accv = bconv[tid];
        for (int n = 0; n < NN; n++) accv += xsb[n] * Wconv[tid * NN + n];
        out[(size_t)b * CC + tid] = accv;
    }
    __syncthreads();
}

// ---------------------------------------------------------------------------
// fused kernel: grid 512, block 256, TB=8 batches/block, 2 blocks/SM.
// ---------------------------------------------------------------------------
__global__ void __launch_bounds__(256, 2) fused_gcn(
    const float* __restrict__ real, const float* __restrict__ graph,
    const float* __restrict__ W1, const float* __restrict__ b1,
    const float* __restrict__ W2, const float* __restrict__ b2,
    const float* __restrict__ Wlin, const float* __restrict__ blin,
    const float* __restrict__ Wconv, const float* __restrict__ bconv,
    float* __restrict__ out)
{
    // buf layout (time-multiplexed):
    //   phase A/B1: usT [512][SB] floats at 0          (20480 B)
    //   reductions: red64 [8 kh][4 p][128 f] u64 at 0  (32768 B)
    //   h1T [128][SB] floats at 32768                  ( 5120 B)
    //   fallback: 36728 B from 0
    __shared__ __align__(16) char buf[38400];
    __shared__ float xp[8][4];
    __shared__ float xs[TB];
    __shared__ float wsum[CC];
    __shared__ int   flagS[TB];

    float* usT   = (float*)buf;
    u64t*  red64 = (u64t*)buf;
    float* h1T   = (float*)(buf + 32768);

    const int tid  = threadIdx.x;
    const int b0   = blockIdx.x * TB;
    const int w    = tid >> 5;          // warp 0..7
    const int lane = tid & 31;
    const int f4   = lane * 4;

    if (tid < TB) flagS[tid] = 1;
    if (tid < CC) {
        float a = 0.f;
        #pragma unroll
        for (int n = 0; n < NN; n++) a += Wconv[tid * NN + n];
        wsum[tid] = a;
    }
    __syncthreads();

    // ---- Phase A1: graph density flags (coalesced float4, 5 bands summed)
    for (int i = tid; i < TB * 225; i += 256) {
        int b = i / 225, idx = i - b * 225;
        const float4* g4 = (const float4*)(graph + (size_t)(b0 + b) * (BANDS * NN * NN));
        float4 a0 = g4[idx];
        float4 a1 = g4[225 + idx];
        float4 a2 = g4[450 + idx];
        float4 a3 = g4[675 + idx];
        float4 a4 = g4[900 + idx];
        float s[4];
        s[0] = a0.x + a1.x + a2.x + a3.x + a4.x;
        s[1] = a0.y + a1.y + a2.y + a3.y + a4.y;
        s[2] = a0.z + a1.z + a2.z + a3.z + a4.z;
        s[3] = a0.w + a1.w + a2.w + a3.w + a4.w;
        bool bad = false;
        #pragma unroll
        for (int j = 0; j < 4; j++) {
            int p = idx * 4 + j;
            int n = p / NN, m = p - n * NN;
            if (n != m && s[j] * 0.2f == 0.0f) bad = true;
        }
        if (bad) flagS[b] = 0;
    }

    // ---- Phase A2: colsum of real[b0+w] (warp w owns batch w), write k-major
    {
        const float4* rb4 = (const float4*)(real + (size_t)(b0 + w) * NN * IN_C);
        float4 a0 = make_float4(0.f, 0.f, 0.f, 0.f);
        float4 a1 = a0, a2 = a0, a3 = a0;
        #pragma unroll 5
        for (int n = 0; n < NN; n++) {
            const float4* row = rb4 + n * (IN_C / 4);
            float4 v0 = row[lane];
            float4 v1 = row[lane + 32];
            float4 v2 = row[lane + 64];
            float4 v3 = row[lane + 96];
            a0.x += v0.x; a0.y += v0.y; a0.z += v0.z; a0.w += v0.w;
            a1.x += v1.x; a1.y += v1.y; a1.z += v1.z; a1.w += v1.w;
            a2.x += v2.x; a2.y += v2.y; a2.z += v2.z; a2.w += v2.w;
            a3.x += v3.x; a3.y += v3.y; a3.z += v3.z; a3.w += v3.w;
        }
        float4 av[4] = {a0, a1, a2, a3};
        #pragma unroll
        for (int i = 0; i < 4; i++) {
            int kbase = (lane + 32 * i) * 4;
            usT[(kbase + 0) * SB + w] = av[i].x;
            usT[(kbase + 1) * SB + w] = av[i].y;
            usT[(kbase + 2) * SB + w] = av[i].z;
            usT[(kbase + 3) * SB + w] = av[i].w;
        }
    }
    __syncthreads();

    // ---- Phase B1: layer-1 partials. Warp w covers k in [64w, 64w+64).
    // acc[p][j]: batch pair {2p,2p+1}, feature f4+j.
    u64t acc[4][4];
    #pragma unroll
    for (int p = 0; p < 4; p++)
        #pragma unroll
        for (int j = 0; j < 4; j++) acc[p][j] = 0ull;
    {
        const int kbeg = w * 64;
        #pragma unroll 2
        for (int ki = 0; ki < 64; ki++) {
            int k = kbeg + ki;
            const float* ub = &usT[k * SB];
            u64t u0 = *(const u64t*)(ub + 0);
            u64t u1 = *(const u64t*)(ub + 2);
            u64t u2 = *(const u64t*)(ub + 4);
            u64t u3 = *(const u64t*)(ub + 6);
            float4 wv = *(const float4*)(W1 + k * FF + f4);
            u64t w0 = pk2(wv.x, wv.x), w1 = pk2(wv.y, wv.y);
            u64t w2 = pk2(wv.z, wv.z), w3 = pk2(wv.w, wv.w);
            fma2(acc[0][0], u0, w0); fma2(acc[1][0], u1, w0);
            fma2(acc[2][0], u2, w0); fma2(acc[3][0], u3, w0);
            fma2(acc[0][1], u0, w1); fma2(acc[1][1], u1, w1);
            fma2(acc[2][1], u2, w1); fma2(acc[3][1], u3, w1);
            fma2(acc[0][2], u0, w2); fma2(acc[1][2], u1, w2);
            fma2(acc[2][2], u2, w2); fma2(acc[3][2], u3, w2);
            fma2(acc[0][3], u0, w3); fma2(acc[1][3], u1, w3);
            fma2(acc[2][3], u2, w3); fma2(acc[3][3], u3, w3);
        }
    }
    __syncthreads();   // all usT reads complete before red64 overwrites
    #pragma unroll
    for (int p = 0; p < 4; p++)
        #pragma unroll
        for (int j = 0; j < 4; j++)
            red64[w * 512 + p * 128 + f4 + j] = acc[p][j];
    __syncthreads();

    // ---- reduce kh -> h1T. Thread t: f = t&127, handles p = t>>7 and +2.
    {
        const float s1 = 1.0f / 30.0f;
        int fr = tid & 127, pp = tid >> 7;
        float bb = b1[fr];
        #pragma unroll
        for (int pi = 0; pi < 2; pi++) {
            int p = pp + 2 * pi;
            float lo = 0.f, hi = 0.f;
            #pragma unroll
            for (int kh = 0; kh < 8; kh++) {
                float a, b; upk2(a, b, red64[kh * 512 + p * 128 + fr]);
                lo += a; hi += b;
            }
            h1T[fr * SB + 2 * p]     = fmaxf(fmaf(s1, lo, bb), 0.0f);
            h1T[fr * SB + 2 * p + 1] = fmaxf(fmaf(s1, hi, bb), 0.0f);
        }
    }
    __syncthreads();

    // ---- Phase B2: layer-2 partials. Warp w covers k in [16w, 16w+16).
    #pragma unroll
    for (int p = 0; p < 4; p++)
        #pragma unroll
        for (int j = 0; j < 4; j++) acc[p][j] = 0ull;
    {
        const int kbeg = w * 16;
        #pragma unroll 2
        for (int ki = 0; ki < 16; ki++) {
            int k = kbeg + ki;
            const float* ub = &h1T[k * SB];
            u64t u0 = *(const u64t*)(ub + 0);
            u64t u1 = *(const u64t*)(ub + 2);
            u64t u2 = *(const u64t*)(ub + 4);
            u64t u3 = *(const u64t*)(ub + 6);
            float4 wv = *(const float4*)(W2 + k * FF + f4);
            u64t w0 = pk2(wv.x, wv.x), w1 = pk2(wv.y, wv.y);
            u64t w2 = pk2(wv.z, wv.z), w3 = pk2(wv.w, wv.w);
            fma2(acc[0][0], u0, w0); fma2(acc[1][0], u1, w0);
            fma2(acc[2][0], u2, w0); fma2(acc[3][0], u3, w0);
            fma2(acc[0][1], u0, w1); fma2(acc[1][1], u1, w1);
            fma2(acc[2][1], u2, w1); fma2(acc[3][1], u3, w1);
            fma2(acc[0][2], u0, w2); fma2(acc[1][2], u1, w2);
            fma2(acc[2][2], u2, w2); fma2(acc[3][2], u3, w2);
            fma2(acc[0][3], u0, w3); fma2(acc[1][3], u1, w3);
            fma2(acc[2][3], u2, w3); fma2(acc[3][3], u3, w3);
        }
    }
    __syncthreads();   // h1T reads done (red64 write below doesn't touch h1T)
    #pragma unroll
    for (int p = 0; p < 4; p++)
        #pragma unroll
        for (int j = 0; j < 4; j++)
            red64[w * 512 + p * 128 + f4 + j] = acc[p][j];
    __syncthreads();

    // ---- final reduce + epilogue. Thread t: f = t&127, p = t>>7 and +2.
    {
        int fr = tid & 127, pp = tid >> 7;
        float bb = b2[fr];
        float wl = Wlin[fr];
        float part[4];                     // {p1.lo, p1.hi, p2.lo, p2.hi}
        #pragma unroll
        for (int pi = 0; pi < 2; pi++) {
            int p = pp + 2 * pi;
            float lo = 0.f, hi = 0.f;
            #pragma unroll
            for (int kh = 0; kh < 8; kh++) {
                float a, b; upk2(a, b, red64[kh * 512 + p * 128 + fr]);
                lo += a; hi += b;
            }
            part[2 * pi]     = fmaxf(lo + bb, 0.0f) * wl;
            part[2 * pi + 1] = fmaxf(hi + bb, 0.0f) * wl;
        }
        #pragma unroll
        for (int off = 16; off > 0; off >>= 1)
            #pragma unroll
            for (int c = 0; c < 4; c++)
                part[c] += __shfl_xor_sync(0xffffffffu, part[c], off);
        if (lane == 0) {
            xp[w][0] = part[0]; xp[w][1] = part[1];
            xp[w][2] = part[2]; xp[w][3] = part[3];
        }
    }
    __syncthreads();
    if (tid < TB) {
        int b = tid;
        int pp = (b >> 1) & 1;             // warps pp*4..pp*4+3 hold this batch
        int slot = (b & 1) + ((b >> 2) << 1);
        float s = xp[pp * 4 + 0][slot] + xp[pp * 4 + 1][slot]
                + xp[pp * 4 + 2][slot] + xp[pp * 4 + 3][slot];
        xs[b] = fmaxf(s + blin[0], 0.0f);
    }
    __syncthreads();

    if (tid < TB * CC) {
        int b = tid / CC, c = tid - b * CC;
        if (flagS[b])
            out[(size_t)(b0 + b) * CC + c] = xs[b] * wsum[c] + bconv[c];
    }
    __syncthreads();

    // ---- honest fallback for any non-dense batch (uniform branch)
    for (int fb = 0; fb < TB; fb++) {
        if (!flagS[fb]) {
            fallback_batch(b0 + fb, buf, tid, real, graph, W1, b1, W2, b2,
                           Wlin, blin, Wconv, bconv, out);
        }
    }
}

// ---------------------------------------------------------------------------
extern "C" void kernel_launch(void* const* d_in, const int* in_sizes, int n_in,
                              void* d_out, int out_size)
{
    const float* real  = (const float*)d_in[0];
    const float* graph = (const float*)d_in[2];
    const float* W1    = (const float*)d_in[3];
    const float* b1    = (const float*)d_in[4];
    const float* W2    = (const float*)d_in[5];
    const float* b2    = (const float*)d_in[6];
    const float* Wlin  = (const float*)d_in[7];
    const float* blin  = (const float*)d_in[8];
    const float* Wconv = (const float*)d_in[9];
    const float* bconv = (const float*)d_in[10];
    float* out = (float*)d_out;

    fused_gcn<<<B_TOT / TB, 256>>>(real, graph, W1, b1, W2, b2, Wlin, blin,
                                   Wconv, bconv, out);
}

// round 6
// speedup vs baseline: 1.6165x; 1.1844x over previous
#include <cuda_runtime.h>
#include <cstdint>

// ---------------------------------------------------------------------------
// GCNNet fused single-kernel implementation.
// An = D^-1/2 (A+I) D^-1/2, A = (mean_bands(graph) != 0). Dense pattern
// (measure-1 for Gaussian graph) => An = (1/30)*J (rank-1):
//   h1 = relu((1/30) colsum(real) @ W1 + b1)      (all rows identical)
//   h2 = relu(h1 @ W2 + b2)                       (An row-sums == 1)
//   x  = relu(h2 . Wlin + blin); out[c] = x * rowsum(Wconv[c]) + bconv[c]
// Phase A: per-block flags + colsums (DRAM-bound, overlaps other blocks' B)
// Phase B: FFMA2 MLP, K split across 8 warps, depth-4 W prefetch pipeline.
// ---------------------------------------------------------------------------

#define B_TOT   4096
#define BANDS   5
#define NN      30
#define IN_C    512
#define FF      128
#define CC      9
#define TB      8             // batches per block
#define SB      10            // padded batch stride (floats) in k-major smem

typedef unsigned long long u64t;

// ---- f32x2 helpers --------------------------------------------------------
__device__ __forceinline__ u64t pk2(float lo, float hi) {
    u64t r; asm("mov.b64 %0,{%1,%2};" : "=l"(r) : "f"(lo), "f"(hi)); return r;
}
__device__ __forceinline__ void upk2(float& lo, float& hi, u64t v) {
    asm("mov.b64 {%0,%1},%2;" : "=f"(lo), "=f"(hi) : "l"(v));
}
__device__ __forceinline__ void fma2(u64t& d, u64t a, u64t b) {
    asm("fma.rn.f32x2 %0,%1,%2,%0;" : "+l"(d) : "l"(a), "l"(b));
}

// ---------------------------------------------------------------------------
// honest fallback for one non-dense batch; whole block (256 thr), smem 'buf'
// (>= 36728 bytes) is reused.
// ---------------------------------------------------------------------------
__device__ void fallback_batch(
    int b, char* buf, int tid,
    const float* __restrict__ real, const float* __restrict__ graph,
    const float* __restrict__ W1, const float* __restrict__ b1,
    const float* __restrict__ W2, const float* __restrict__ b2,
    const float* __restrict__ Wlin, const float* __restrict__ blin,
    const float* __restrict__ Wconv, const float* __restrict__ bconv,
    float* __restrict__ out)
{
    float* An   = (float*)buf;          // 900 (pad to 960 incl. dinv)
    float* dinv = An + 900;             // 30
    float* Ys   = An + 960;             // 3840
    float* Hs   = Ys + 3840;            // 3840
    float* rrow = Hs + 3840;            // 512
    float* xsb  = rrow + 512;           // 30     total 9182 floats = 36728 B

    const float* g = graph + (size_t)b * (BANDS * NN * NN);
    for (int p = tid; p < NN * NN; p += 256) {
        int n = p / NN, m = p - n * NN;
        float s5 = g[p] + g[900 + p] + g[1800 + p] + g[2700 + p] + g[3600 + p];
        float a = (s5 * 0.2f != 0.0f) ? 1.0f : 0.0f;
        if (n == m) a = 1.0f;
        An[p] = a;
    }
    __syncthreads();
    if (tid < NN) {
        float dg = 0.f;
        for (int m = 0; m < NN; m++) dg += An[tid * NN + m];
        dinv[tid] = (dg > 0.f) ? rsqrtf(dg) : 0.0f;
    }
    __syncthreads();
    for (int p = tid; p < NN * NN; p += 256) {
        int n = p / NN, m = p - n * NN;
        An[p] = dinv[n] * An[p] * dinv[m];
    }
    __syncthreads();

    const float* rb = real + (size_t)b * NN * IN_C;
    for (int n = 0; n < NN; n++) {
        for (int c = tid; c < IN_C; c += 256) rrow[c] = rb[n * IN_C + c];
        __syncthreads();
        if (tid < FF) {
            float accv = 0.f;
            for (int c = 0; c < IN_C; c++) accv += rrow[c] * W1[c * FF + tid];
            Ys[n * FF + tid] = accv;
        }
        __syncthreads();
    }
    if (tid < FF) {
        float bb = b1[tid];
        for (int n = 0; n < NN; n++) {
            float accv = 0.f;
            for (int m = 0; m < NN; m++) accv += An[n * NN + m] * Ys[m * FF + tid];
            Hs[n * FF + tid] = fmaxf(accv + bb, 0.0f);
        }
    }
    __syncthreads();
    if (tid < FF) {
        for (int n = 0; n < NN; n++) {
            float accv = 0.f;
            for (int c = 0; c < FF; c++) accv += Hs[n * FF + c] * W2[c * FF + tid];
            Ys[n * FF + tid] = accv;
        }
    }
    __syncthreads();
    if (tid < FF) {
        float bb = b2[tid];
        for (int n = 0; n < NN; n++) {
            float accv = 0.f;
            for (int m = 0; m < NN; m++) accv += An[n * NN + m] * Ys[m * FF + tid];
            Hs[n * FF + tid] = fmaxf(accv + bb, 0.0f);
        }
    }
    __syncthreads();
    if (tid < NN) {
        float accv = 0.f;
        for (int ff = 0; ff < FF; ff++) accv += Hs[tid * FF + ff] * Wlin[ff];
        xsb[tid] = fmaxf(accv + blin[0], 0.0f);
    }
    __syncthreads();
    if (tid < CC) {
        float accv = bconv[tid];
        for (int n = 0; n < NN; n++) accv += xsb[n] * Wconv[tid * NN + n];
        out[(size_t)b * CC + tid] = accv;
    }
    __syncthreads();
}

// ---------------------------------------------------------------------------
// fused kernel: grid 512, block 256, TB=8 batches/block, 2 blocks/SM.
// ---------------------------------------------------------------------------
__global__ void __launch_bounds__(256, 2) fused_gcn(
    const float* __restrict__ real, const float* __restrict__ graph,
    const float* __restrict__ W1, const float* __restrict__ b1,
    const float* __restrict__ W2, const float* __restrict__ b2,
    const float* __restrict__ Wlin, const float* __restrict__ blin,
    const float* __restrict__ Wconv, const float* __restrict__ bconv,
    float* __restrict__ out)
{
    // buf layout (time-multiplexed):
    //   phase A/B1: usT [512][SB] floats at 0          (20480 B)
    //   reductions: red64 [8 kh][4 p][128 f] u64 at 0  (32768 B)
    //   h1T [128][SB] floats at 32768                  ( 5120 B)
    //   fallback: 36728 B from 0
    __shared__ __align__(16) char buf[38400];
    __shared__ float xp[8][4];
    __shared__ float xs[TB];
    __shared__ float wsum[CC];
    __shared__ int   flagS[TB];

    float* usT   = (float*)buf;
    u64t*  red64 = (u64t*)buf;
    float* h1T   = (float*)(buf + 32768);

    const int tid  = threadIdx.x;
    const int b0   = blockIdx.x * TB;
    const int w    = tid >> 5;          // warp 0..7
    const int lane = tid & 31;
    const int f4   = lane * 4;

    if (tid < TB) flagS[tid] = 1;
    if (tid < CC) {
        float a = 0.f;
        #pragma unroll
        for (int n = 0; n < NN; n++) a += Wconv[tid * NN + n];
        wsum[tid] = a;
    }
    __syncthreads();

    // ---- Phase A1: graph density flags (coalesced float4, 5 bands summed)
    for (int i = tid; i < TB * 225; i += 256) {
        int b = i / 225, idx = i - b * 225;
        const float4* g4 = (const float4*)(graph + (size_t)(b0 + b) * (BANDS * NN * NN));
        float4 a0 = g4[idx];
        float4 a1 = g4[225 + idx];
        float4 a2 = g4[450 + idx];
        float4 a3 = g4[675 + idx];
        float4 a4 = g4[900 + idx];
        float s[4];
        s[0] = a0.x + a1.x + a2.x + a3.x + a4.x;
        s[1] = a0.y + a1.y + a2.y + a3.y + a4.y;
        s[2] = a0.z + a1.z + a2.z + a3.z + a4.z;
        s[3] = a0.w + a1.w + a2.w + a3.w + a4.w;
        bool bad = false;
        #pragma unroll
        for (int j = 0; j < 4; j++) {
            int p = idx * 4 + j;
            int n = p / NN, m = p - n * NN;
            if (n != m && s[j] * 0.2f == 0.0f) bad = true;
        }
        if (bad) flagS[b] = 0;
    }

    // ---- Phase A2: colsum of real[b0+w] (warp w owns batch w), write k-major
    {
        const float4* rb4 = (const float4*)(real + (size_t)(b0 + w) * NN * IN_C);
        float4 a0 = make_float4(0.f, 0.f, 0.f, 0.f);
        float4 a1 = a0, a2 = a0, a3 = a0;
        #pragma unroll 5
        for (int n = 0; n < NN; n++) {
            const float4* row = rb4 + n * (IN_C / 4);
            float4 v0 = row[lane];
            float4 v1 = row[lane + 32];
            float4 v2 = row[lane + 64];
            float4 v3 = row[lane + 96];
            a0.x += v0.x; a0.y += v0.y; a0.z += v0.z; a0.w += v0.w;
            a1.x += v1.x; a1.y += v1.y; a1.z += v1.z; a1.w += v1.w;
            a2.x += v2.x; a2.y += v2.y; a2.z += v2.z; a2.w += v2.w;
            a3.x += v3.x; a3.y += v3.y; a3.z += v3.z; a3.w += v3.w;
        }
        float4 av[4] = {a0, a1, a2, a3};
        #pragma unroll
        for (int i = 0; i < 4; i++) {
            int kbase = (lane + 32 * i) * 4;
            usT[(kbase + 0) * SB + w] = av[i].x;
            usT[(kbase + 1) * SB + w] = av[i].y;
            usT[(kbase + 2) * SB + w] = av[i].z;
            usT[(kbase + 3) * SB + w] = av[i].w;
        }
    }
    __syncthreads();

    // ---- Phase B1: layer-1 partials. Warp w covers k in [64w, 64w+64).
    // acc[p][j]: batch pair {2p,2p+1}, feature f4+j.
    // W rows come from L2 (~250cy): depth-4 explicit prefetch ring hides it.
    u64t acc[4][4];
    #pragma unroll
    for (int p = 0; p < 4; p++)
        #pragma unroll
        for (int j = 0; j < 4; j++) acc[p][j] = 0ull;
    {
        const int kbeg = w * 64;
        const float4* Wp = (const float4*)(W1 + (size_t)kbeg * FF) + lane;
        float4 wpf[4];
        #pragma unroll
        for (int s = 0; s < 4; s++) wpf[s] = Wp[s * (FF / 4)];
        #pragma unroll 4
        for (int ki = 0; ki < 64; ki++) {
            float4 wv = wpf[ki & 3];
            int kn = (ki + 4 < 64) ? (ki + 4) : ki;   // tail: harmless reload
            wpf[ki & 3] = Wp[kn * (FF / 4)];
            const float* ub = &usT[(kbeg + ki) * SB];
            u64t u0 = *(const u64t*)(ub + 0);
            u64t u1 = *(const u64t*)(ub + 2);
            u64t u2 = *(const u64t*)(ub + 4);
            u64t u3 = *(const u64t*)(ub + 6);
            u64t w0 = pk2(wv.x, wv.x), w1 = pk2(wv.y, wv.y);
            u64t w2 = pk2(wv.z, wv.z), w3 = pk2(wv.w, wv.w);
            fma2(acc[0][0], u0, w0); fma2(acc[1][0], u1, w0);
            fma2(acc[2][0], u2, w0); fma2(acc[3][0], u3, w0);
            fma2(acc[0][1], u0, w1); fma2(acc[1][1], u1, w1);
            fma2(acc[2][1], u2, w1); fma2(acc[3][1], u3, w1);
            fma2(acc[0][2], u0, w2); fma2(acc[1][2], u1, w2);
            fma2(acc[2][2], u2, w2); fma2(acc[3][2], u3, w2);
            fma2(acc[0][3], u0, w3); fma2(acc[1][3], u1, w3);
            fma2(acc[2][3], u2, w3); fma2(acc[3][3], u3, w3);
        }
    }
    __syncthreads();   // all usT reads complete before red64 overwrites
    #pragma unroll
    for (int p = 0; p < 4; p++)
        #pragma unroll
        for (int j = 0; j < 4; j++)
            red64[w * 512 + p * 128 + f4 + j] = acc[p][j];
    __syncthreads();

    // ---- reduce kh -> h1T. Thread t: f = t&127, handles p = t>>7 and +2.
    {
        const float s1 = 1.0f / 30.0f;
        int fr = tid & 127, pp = tid >> 7;
        float bb = b1[fr];
        #pragma unroll
        for (int pi = 0; pi < 2; pi++) {
            int p = pp + 2 * pi;
            float lo = 0.f, hi = 0.f;
            #pragma unroll
            for (int kh = 0; kh < 8; kh++) {
                float a, b; upk2(a, b, red64[kh * 512 + p * 128 + fr]);
                lo += a; hi += b;
            }
            h1T[fr * SB + 2 * p]     = fmaxf(fmaf(s1, lo, bb), 0.0f);
            h1T[fr * SB + 2 * p + 1] = fmaxf(fmaf(s1, hi, bb), 0.0f);
        }
    }
    __syncthreads();

    // ---- Phase B2: layer-2 partials. Warp w covers k in [16w, 16w+16).
    #pragma unroll
    for (int p = 0; p < 4; p++)
        #pragma unroll
        for (int j = 0; j < 4; j++) acc[p][j] = 0ull;
    {
        const int kbeg = w * 16;
        const float4* Wp = (const float4*)(W2 + (size_t)kbeg * FF) + lane;
        float4 wpf[4];
        #pragma unroll
        for (int s = 0; s < 4; s++) wpf[s] = Wp[s * (FF / 4)];
        #pragma unroll 4
        for (int ki = 0; ki < 16; ki++) {
            float4 wv = wpf[ki & 3];
            int kn = (ki + 4 < 16) ? (ki + 4) : ki;
            wpf[ki & 3] = Wp[kn * (FF / 4)];
            const float* ub = &h1T[(kbeg + ki) * SB];
            u64t u0 = *(const u64t*)(ub + 0);
            u64t u1 = *(const u64t*)(ub + 2);
            u64t u2 = *(const u64t*)(ub + 4);
            u64t u3 = *(const u64t*)(ub + 6);
            u64t w0 = pk2(wv.x, wv.x), w1 = pk2(wv.y, wv.y);
            u64t w2 = pk2(wv.z, wv.z), w3 = pk2(wv.w, wv.w);
            fma2(acc[0][0], u0, w0); fma2(acc[1][0], u1, w0);
            fma2(acc[2][0], u2, w0); fma2(acc[3][0], u3, w0);
            fma2(acc[0][1], u0, w1); fma2(acc[1][1], u1, w1);
            fma2(acc[2][1], u2, w1); fma2(acc[3][1], u3, w1);
            fma2(acc[0][2], u0, w2); fma2(acc[1][2], u1, w2);
            fma2(acc[2][2], u2, w2); fma2(acc[3][2], u3, w2);
            fma2(acc[0][3], u0, w3); fma2(acc[1][3], u1, w3);
            fma2(acc[2][3], u2, w3); fma2(acc[3][3], u3, w3);
        }
    }
    __syncthreads();   // h1T reads done (red64 write below doesn't touch h1T)
    #pragma unroll
    for (int p = 0; p < 4; p++)
        #pragma unroll
        for (int j = 0; j < 4; j++)
            red64[w * 512 + p * 128 + f4 + j] = acc[p][j];
    __syncthreads();

    // ---- final reduce + epilogue. Thread t: f = t&127, p = t>>7 and +2.
    {
        int fr = tid & 127, pp = tid >> 7;
        float bb = b2[fr];
        float wl = Wlin[fr];
        float part[4];                     // {p1.lo, p1.hi, p2.lo, p2.hi}
        #pragma unroll
        for (int pi = 0; pi < 2; pi++) {
            int p = pp + 2 * pi;
            float lo = 0.f, hi = 0.f;
            #pragma unroll
            for (int kh = 0; kh < 8; kh++) {
                float a, b; upk2(a, b, red64[kh * 512 + p * 128 + fr]);
                lo += a; hi += b;
            }
            part[2 * pi]     = fmaxf(lo + bb, 0.0f) * wl;
            part[2 * pi + 1] = fmaxf(hi + bb, 0.0f) * wl;
        }
        #pragma unroll
        for (int off = 16; off > 0; off >>= 1)
            #pragma unroll
            for (int c = 0; c < 4; c++)
                part[c] += __shfl_xor_sync(0xffffffffu, part[c], off);
        if (lane == 0) {
            xp[w][0] = part[0]; xp[w][1] = part[1];
            xp[w][2] = part[2]; xp[w][3] = part[3];
        }
    }
    __syncthreads();
    if (tid < TB) {
        int b = tid;
        int pp = (b >> 1) & 1;             // warps pp*4..pp*4+3 hold this batch
        int slot = (b & 1) + ((b >> 2) << 1);
        float s = xp[pp * 4 + 0][slot] + xp[pp * 4 + 1][slot]
                + xp[pp * 4 + 2][slot] + xp[pp * 4 + 3][slot];
        xs[b] = fmaxf(s + blin[0], 0.0f);
    }
    __syncthreads();

    if (tid < TB * CC) {
        int b = tid / CC, c = tid - b * CC;
        if (flagS[b])
            out[(size_t)(b0 + b) * CC + c] = xs[b] * wsum[c] + bconv[c];
    }
    __syncthreads();

    // ---- honest fallback for any non-dense batch (uniform branch)
    for (int fb = 0; fb < TB; fb++) {
        if (!flagS[fb]) {
            fallback_batch(b0 + fb, buf, tid, real, graph, W1, b1, W2, b2,
                           Wlin, blin, Wconv, bconv, out);
        }
    }
}

// ---------------------------------------------------------------------------
extern "C" void kernel_launch(void* const* d_in, const int* in_sizes, int n_in,
                              void* d_out, int out_size)
{
    const float* real  = (const float*)d_in[0];
    const float* graph = (const float*)d_in[2];
    const float* W1    = (const float*)d_in[3];
    const float* b1    = (const float*)d_in[4];
    const float* W2    = (const float*)d_in[5];
    const float* b2    = (const float*)d_in[6];
    const float* Wlin  = (const float*)d_in[7];
    const float* blin  = (const float*)d_in[8];
    const float* Wconv = (const float*)d_in[9];
    const float* bconv = (const float*)d_in[10];
    float* out = (float*)d_out;

    fused_gcn<<<B_TOT / TB, 256>>>(real, graph, W1, b1, W2, b2, Wlin, blin,
                                   Wconv, bconv, out);
}

// round 7
// speedup vs baseline: 1.6564x; 1.0247x over previous
#include <cuda_runtime.h>
#include <cstdint>

// ---------------------------------------------------------------------------
// GCNNet fused single-kernel implementation.
// An = D^-1/2 (A+I) D^-1/2, A = (mean_bands(graph) != 0). Dense pattern
// (measure-1 for Gaussian graph) => An = (1/30)*J (rank-1):
//   h1 = relu((1/30) colsum(real) @ W1 + b1)      (all rows identical)
//   h2 = relu(h1 @ W2 + b2)                       (An row-sums == 1)
//   x  = relu(h2 . Wlin + blin); out[c] = x * rowsum(Wconv[c]) + bconv[c]
// Grid 512 blocks @ 4 blocks/SM -> whole grid co-resident (1 wave):
// memory phases of some blocks always overlap compute phases of others.
// Warp split: kh (4-way K) x bh (2-way batch). acc = 16 regs, ring depth 2.
// ---------------------------------------------------------------------------

#define B_TOT   4096
#define BANDS   5
#define NN      30
#define IN_C    512
#define FF      128
#define CC      9
#define TB      8             // batches per block
#define SB      10            // padded batch stride (floats) in k-major smem

typedef unsigned long long u64t;

// ---- f32x2 helpers --------------------------------------------------------
__device__ __forceinline__ u64t pk2(float lo, float hi) {
    u64t r; asm("mov.b64 %0,{%1,%2};" : "=l"(r) : "f"(lo), "f"(hi)); return r;
}
__device__ __forceinline__ void upk2(float& lo, float& hi, u64t v) {
    asm("mov.b64 {%0,%1},%2;" : "=f"(lo), "=f"(hi) : "l"(v));
}
__device__ __forceinline__ void fma2(u64t& d, u64t a, u64t b) {
    asm("fma.rn.f32x2 %0,%1,%2,%0;" : "+l"(d) : "l"(a), "l"(b));
}

// ---------------------------------------------------------------------------
// honest fallback for one non-dense batch; whole block (256 thr), smem 'buf'
// (>= 36728 bytes) is reused.
// ---------------------------------------------------------------------------
__device__ void fallback_batch(
    int b, char* buf, int tid,
    const float* __restrict__ real, const float* __restrict__ graph,
    const float* __restrict__ W1, const float* __restrict__ b1,
    const float* __restrict__ W2, const float* __restrict__ b2,
    const float* __restrict__ Wlin, const float* __restrict__ blin,
    const float* __restrict__ Wconv, const float* __restrict__ bconv,
    float* __restrict__ out)
{
    float* An   = (float*)buf;          // 900 (pad to 960 incl. dinv)
    float* dinv = An + 900;             // 30
    float* Ys   = An + 960;             // 3840
    float* Hs   = Ys + 3840;            // 3840
    float* rrow = Hs + 3840;            // 512
    float* xsb  = rrow + 512;           // 30     total 9182 floats = 36728 B

    const float* g = graph + (size_t)b * (BANDS * NN * NN);
    for (int p = tid; p < NN * NN; p += 256) {
        int n = p / NN, m = p - n * NN;
        float s5 = g[p] + g[900 + p] + g[1800 + p] + g[2700 + p] + g[3600 + p];
        float a = (s5 * 0.2f != 0.0f) ? 1.0f : 0.0f;
        if (n == m) a = 1.0f;
        An[p] = a;
    }
    __syncthreads();
    if (tid < NN) {
        float dg = 0.f;
        for (int m = 0; m < NN; m++) dg += An[tid * NN + m];
        dinv[tid] = (dg > 0.f) ? rsqrtf(dg) : 0.0f;
    }
    __syncthreads();
    for (int p = tid; p < NN * NN; p += 256) {
        int n = p / NN, m = p - n * NN;
        An[p] = dinv[n] * An[p] * dinv[m];
    }
    __syncthreads();

    const float* rb = real + (size_t)b * NN * IN_C;
    for (int n = 0; n < NN; n++) {
        for (int c = tid; c < IN_C; c += 256) rrow[c] = rb[n * IN_C + c];
        __syncthreads();
        if (tid < FF) {
            float accv = 0.f;
            for (int c = 0; c < IN_C; c++) accv += rrow[c] * W1[c * FF + tid];
            Ys[n * FF + tid] = accv;
        }
        __syncthreads();
    }
    if (tid < FF) {
        float bb = b1[tid];
        for (int n = 0; n < NN; n++) {
            float accv = 0.f;
            for (int m = 0; m < NN; m++) accv += An[n * NN + m] * Ys[m * FF + tid];
            Hs[n * FF + tid] = fmaxf(accv + bb, 0.0f);
        }
    }
    __syncthreads();
    if (tid < FF) {
        for (int n = 0; n < NN; n++) {
            float accv = 0.f;
            for (int c = 0; c < FF; c++) accv += Hs[n * FF + c] * W2[c * FF + tid];
            Ys[n * FF + tid] = accv;
        }
    }
    __syncthreads();
    if (tid < FF) {
        float bb = b2[tid];
        for (int n = 0; n < NN; n++) {
            float accv = 0.f;
            for (int m = 0; m < NN; m++) accv += An[n * NN + m] * Ys[m * FF + tid];
            Hs[n * FF + tid] = fmaxf(accv + bb, 0.0f);
        }
    }
    __syncthreads();
    if (tid < NN) {
        float accv = 0.f;
        for (int ff = 0; ff < FF; ff++) accv += Hs[tid * FF + ff] * Wlin[ff];
        xsb[tid] = fmaxf(accv + blin[0], 0.0f);
    }
    __syncthreads();
    if (tid < CC) {
        float accv = bconv[tid];
        for (int n = 0; n < NN; n++) accv += xsb[n] * Wconv[tid * NN + n];
        out[(size_t)b * CC + tid] = accv;
    }
    __syncthreads();
}

// ---------------------------------------------------------------------------
// fused kernel: grid 512, block 256, TB=8 batches/block, 4 blocks/SM.
// Warp w: kh = w>>1 (K quarter), bh = w&1 (batch half). Lane: f = 4*lane.
// ---------------------------------------------------------------------------
__global__ void __launch_bounds__(256, 4) fused_gcn(
    const float* __restrict__ real, const float* __restrict__ graph,
    const float* __restrict__ W1, const float* __restrict__ b1,
    const float* __restrict__ W2, const float* __restrict__ b2,
    const float* __restrict__ Wlin, const float* __restrict__ blin,
    const float* __restrict__ Wconv, const float* __restrict__ bconv,
    float* __restrict__ out)
{
    // buf layout (time-multiplexed):
    //   phase A/B: usT [512][SB] floats at 0            (20480 B)
    //   reductions: red64 [4 kh][4 g][128 f] u64 at 0   (16384 B)
    //   h1T [128][SB] floats at 32768                   ( 5120 B)
    //   fallback: 36728 B from 0
    __shared__ __align__(16) char buf[38400];
    __shared__ float xp[8][4];
    __shared__ float xs[TB];
    __shared__ float wsum[CC];
    __shared__ int   flagS[TB];

    float* usT   = (float*)buf;
    u64t*  red64 = (u64t*)buf;
    float* h1T   = (float*)(buf + 32768);

    const int tid  = threadIdx.x;
    const int b0   = blockIdx.x * TB;
    const int w    = tid >> 5;          // warp 0..7
    const int lane = tid & 31;
    const int f4   = lane * 4;
    const int kh   = w >> 1;            // 0..3
    const int bh   = w & 1;             // 0..1

    if (tid < TB) flagS[tid] = 1;
    if (tid < CC) {
        float a = 0.f;
        #pragma unroll
        for (int n = 0; n < NN; n++) a += Wconv[tid * NN + n];
        wsum[tid] = a;
    }
    __syncthreads();

    // ---- Phase A1: graph density flags (coalesced float4, 5 bands summed)
    for (int i = tid; i < TB * 225; i += 256) {
        int b = i / 225, idx = i - b * 225;
        const float4* g4 = (const float4*)(graph + (size_t)(b0 + b) * (BANDS * NN * NN));
        float4 a0 = g4[idx];
        float4 a1 = g4[225 + idx];
        float4 a2 = g4[450 + idx];
        float4 a3 = g4[675 + idx];
        float4 a4 = g4[900 + idx];
        float s[4];
        s[0] = a0.x + a1.x + a2.x + a3.x + a4.x;
        s[1] = a0.y + a1.y + a2.y + a3.y + a4.y;
        s[2] = a0.z + a1.z + a2.z + a3.z + a4.z;
        s[3] = a0.w + a1.w + a2.w + a3.w + a4.w;
        bool bad = false;
        #pragma unroll
        for (int j = 0; j < 4; j++) {
            int p = idx * 4 + j;
            int n = p / NN, m = p - n * NN;
            if (n != m && s[j] * 0.2f == 0.0f) bad = true;
        }
        if (bad) flagS[b] = 0;
    }

    // ---- Phase A2: colsum of real[b0+w] (warp w owns batch w), write k-major
    {
        const float4* rb4 = (const float4*)(real + (size_t)(b0 + w) * NN * IN_C);
        float4 a0 = make_float4(0.f, 0.f, 0.f, 0.f);
        float4 a1 = a0, a2 = a0, a3 = a0;
        #pragma unroll 5
        for (int n = 0; n < NN; n++) {
            const float4* row = rb4 + n * (IN_C / 4);
            float4 v0 = row[lane];
            float4 v1 = row[lane + 32];
            float4 v2 = row[lane + 64];
            float4 v3 = row[lane + 96];
            a0.x += v0.x; a0.y += v0.y; a0.z += v0.z; a0.w += v0.w;
            a1.x += v1.x; a1.y += v1.y; a1.z += v1.z; a1.w += v1.w;
            a2.x += v2.x; a2.y += v2.y; a2.z += v2.z; a2.w += v2.w;
            a3.x += v3.x; a3.y += v3.y; a3.z += v3.z; a3.w += v3.w;
        }
        float4 av[4] = {a0, a1, a2, a3};
        #pragma unroll
        for (int i = 0; i < 4; i++) {
            int kbase = (lane + 32 * i) * 4;
            usT[(kbase + 0) * SB + w] = av[i].x;
            usT[(kbase + 1) * SB + w] = av[i].y;
            usT[(kbase + 2) * SB + w] = av[i].z;
            usT[(kbase + 3) * SB + w] = av[i].w;
        }
    }
    __syncthreads();

    // ---- Phase B1: layer-1 partials. Warp: k in [kh*128, kh*128+128),
    // batches bh*4..bh*4+3 (pairs p=0,1). acc[p][j], feature f4+j.
    u64t acc[2][4];
    #pragma unroll
    for (int p = 0; p < 2; p++)
        #pragma unroll
        for (int j = 0; j < 4; j++) acc[p][j] = 0ull;
    {
        const int kbeg = kh * 128;
        const float4* Wp = (const float4*)(W1 + (size_t)kbeg * FF) + lane;
        float4 wpf[2];
        wpf[0] = Wp[0];
        wpf[1] = Wp[FF / 4];
        #pragma unroll 4
        for (int ki = 0; ki < 128; ki++) {
            float4 wv = wpf[ki & 1];
            int kn = (ki + 2 < 128) ? (ki + 2) : ki;  // tail: harmless reload
            wpf[ki & 1] = Wp[kn * (FF / 4)];
            const float* ub = &usT[(kbeg + ki) * SB + bh * 4];
            u64t u0 = *(const u64t*)(ub + 0);
            u64t u1 = *(const u64t*)(ub + 2);
            u64t w0 = pk2(wv.x, wv.x), w1 = pk2(wv.y, wv.y);
            u64t w2 = pk2(wv.z, wv.z), w3 = pk2(wv.w, wv.w);
            fma2(acc[0][0], u0, w0); fma2(acc[1][0], u1, w0);
            fma2(acc[0][1], u0, w1); fma2(acc[1][1], u1, w1);
            fma2(acc[0][2], u0, w2); fma2(acc[1][2], u1, w2);
            fma2(acc[0][3], u0, w3); fma2(acc[1][3], u1, w3);
        }
    }
    __syncthreads();   // all usT reads complete before red64 overwrites
    // global pair index g = bh*2+p covers batches {2g, 2g+1}
    #pragma unroll
    for (int p = 0; p < 2; p++)
        #pragma unroll
        for (int j = 0; j < 4; j++)
            red64[kh * 512 + (bh * 2 + p) * 128 + f4 + j] = acc[p][j];
    __syncthreads();

    // ---- reduce kh -> h1T. Thread t: f = t&127, gg = t>>7; g = gg, gg+2.
    {
        const float s1 = 1.0f / 30.0f;
        int fr = tid & 127, gg = tid >> 7;
        float bb = b1[fr];
        #pragma unroll
        for (int pi = 0; pi < 2; pi++) {
            int g = gg + 2 * pi;
            float lo = 0.f, hi = 0.f;
            #pragma unroll
            for (int q = 0; q < 4; q++) {
                float a, b; upk2(a, b, red64[q * 512 + g * 128 + fr]);
                lo += a; hi += b;
            }
            h1T[fr * SB + 2 * g]     = fmaxf(fmaf(s1, lo, bb), 0.0f);
            h1T[fr * SB + 2 * g + 1] = fmaxf(fmaf(s1, hi, bb), 0.0f);
        }
    }
    __syncthreads();

    // ---- Phase B2: layer-2 partials. Warp: k in [kh*32, kh*32+32).
    #pragma unroll
    for (int p = 0; p < 2; p++)
        #pragma unroll
        for (int j = 0; j < 4; j++) acc[p][j] = 0ull;
    {
        const int kbeg = kh * 32;
        const float4* Wp = (const float4*)(W2 + (size_t)kbeg * FF) + lane;
        float4 wpf[2];
        wpf[0] = Wp[0];
        wpf[1] = Wp[FF / 4];
        #pragma unroll 4
        for (int ki = 0; ki < 32; ki++) {
            float4 wv = wpf[ki & 1];
            int kn = (ki + 2 < 32) ? (ki + 2) : ki;
            wpf[ki & 1] = Wp[kn * (FF / 4)];
            const float* ub = &h1T[(kbeg + ki) * SB + bh * 4];
            u64t u0 = *(const u64t*)(ub + 0);
            u64t u1 = *(const u64t*)(ub + 2);
            u64t w0 = pk2(wv.x, wv.x), w1 = pk2(wv.y, wv.y);
            u64t w2 = pk2(wv.z, wv.z), w3 = pk2(wv.w, wv.w);
            fma2(acc[0][0], u0, w0); fma2(acc[1][0], u1, w0);
            fma2(acc[0][1], u0, w1); fma2(acc[1][1], u1, w1);
            fma2(acc[0][2], u0, w2); fma2(acc[1][2], u1, w2);
            fma2(acc[0][3], u0, w3); fma2(acc[1][3], u1, w3);
        }
    }
    __syncthreads();   // h1T reads done (red64 write below doesn't touch h1T)
    #pragma unroll
    for (int p = 0; p < 2; p++)
        #pragma unroll
        for (int j = 0; j < 4; j++)
            red64[kh * 512 + (bh * 2 + p) * 128 + f4 + j] = acc[p][j];
    __syncthreads();

    // ---- final reduce + epilogue. Thread t: f = t&127, gg = t>>7.
    {
        int fr = tid & 127, gg = tid >> 7;
        float bb = b2[fr];
        float wl = Wlin[fr];
        float part[4];                     // {g=gg: lo,hi ; g=gg+2: lo,hi}
        #pragma unroll
        for (int pi = 0; pi < 2; pi++) {
            int g = gg + 2 * pi;
            float lo = 0.f, hi = 0.f;
            #pragma unroll
            for (int q = 0; q < 4; q++) {
                float a, b; upk2(a, b, red64[q * 512 + g * 128 + fr]);
                lo += a; hi += b;
            }
            part[2 * pi]     = fmaxf(lo + bb, 0.0f) * wl;
            part[2 * pi + 1] = fmaxf(hi + bb, 0.0f) * wl;
        }
        #pragma unroll
        for (int off = 16; off > 0; off >>= 1)
            #pragma unroll
            for (int c = 0; c < 4; c++)
                part[c] += __shfl_xor_sync(0xffffffffu, part[c], off);
        if (lane == 0) {
            xp[w][0] = part[0]; xp[w][1] = part[1];
            xp[w][2] = part[2]; xp[w][3] = part[3];
        }
    }
    __syncthreads();
    if (tid < TB) {
        int b = tid;
        int g  = b >> 1;
        int gg = g & 1;                    // warps gg*4..gg*4+3 hold this g
        int slot = (g >> 1) * 2 + (b & 1);
        float s = xp[gg * 4 + 0][slot] + xp[gg * 4 + 1][slot]
                + xp[gg * 4 + 2][slot] + xp[gg * 4 + 3][slot];
        xs[b] = fmaxf(s + blin[0], 0.0f);
    }
    __syncthreads();

    if (tid < TB * CC) {
        int b = tid / CC, c = tid - b * CC;
        if (flagS[b])
            out[(size_t)(b0 + b) * CC + c] = xs[b] * wsum[c] + bconv[c];
    }
    __syncthreads();

    // ---- honest fallback for any non-dense batch (uniform branch)
    for (int fb = 0; fb < TB; fb++) {
        if (!flagS[fb]) {
            fallback_batch(b0 + fb, buf, tid, real, graph, W1, b1, W2, b2,
                           Wlin, blin, Wconv, bconv, out);
        }
    }
}

// ---------------------------------------------------------------------------
extern "C" void kernel_launch(void* const* d_in, const int* in_sizes, int n_in,
                              void* d_out, int out_size)
{
    const float* real  = (const float*)d_in[0];
    const float* graph = (const float*)d_in[2];
    const float* W1    = (const float*)d_in[3];
    const float* b1    = (const float*)d_in[4];
    const float* W2    = (const float*)d_in[5];
    const float* b2    = (const float*)d_in[6];
    const float* Wlin  = (const float*)d_in[7];
    const float* blin  = (const float*)d_in[8];
    const float* Wconv = (const float*)d_in[9];
    const float* bconv = (const float*)d_in[10];
    float* out = (float*)d_out;

    fused_gcn<<<B_TOT / TB, 256>>>(real, graph, W1, b1, W2, b2, Wlin, blin,
                                   Wconv, bconv, out);
}

// round 8
// speedup vs baseline: 1.8183x; 1.0978x over previous
#include <cuda_runtime.h>
#include <cstdint>

// ---------------------------------------------------------------------------
// GCNNet fused single-kernel implementation.
// An = D^-1/2 (A+I) D^-1/2, A = (mean_bands(graph) != 0). Dense pattern
// (measure-1 for Gaussian graph) => An = (1/30)*J (rank-1):
//   h1 = relu((1/30) colsum(real) @ W1 + b1)      (all rows identical)
//   h2 = relu(h1 @ W2 + b2)                       (An row-sums == 1)
//   x  = relu(h2 . Wlin + blin); out[c] = x * rowsum(Wconv[c]) + bconv[c]
// K is processed in 4 chunks of 128 with double-buffered colsums: each warp
// issues the DRAM loads of chunk c+1 interleaved with the FMA of chunk c,
// so memory streaming and FFMA2 work overlap within every warp.
// ---------------------------------------------------------------------------

#define B_TOT   4096
#define BANDS   5
#define NN      30
#define IN_C    512
#define FF      128
#define CC      9
#define TB      8             // batches per block
#define SB      10            // padded batch stride (floats) in k-major smem

typedef unsigned long long u64t;

// ---- f32x2 helpers --------------------------------------------------------
__device__ __forceinline__ u64t pk2(float lo, float hi) {
    u64t r; asm("mov.b64 %0,{%1,%2};" : "=l"(r) : "f"(lo), "f"(hi)); return r;
}
__device__ __forceinline__ void upk2(float& lo, float& hi, u64t v) {
    asm("mov.b64 {%0,%1},%2;" : "=f"(lo), "=f"(hi) : "l"(v));
}
__device__ __forceinline__ void fma2(u64t& d, u64t a, u64t b) {
    asm("fma.rn.f32x2 %0,%1,%2,%0;" : "+l"(d) : "l"(a), "l"(b));
}

// ---------------------------------------------------------------------------
// honest fallback for one non-dense batch; whole block (256 thr), smem 'buf'
// (>= 36728 bytes) is reused.
// ---------------------------------------------------------------------------
__device__ void fallback_batch(
    int b, char* buf, int tid,
    const float* __restrict__ real, const float* __restrict__ graph,
    const float* __restrict__ W1, const float* __restrict__ b1,
    const float* __restrict__ W2, const float* __restrict__ b2,
    const float* __restrict__ Wlin, const float* __restrict__ blin,
    const float* __restrict__ Wconv, const float* __restrict__ bconv,
    float* __restrict__ out)
{
    float* An   = (float*)buf;          // 900 (pad to 960 incl. dinv)
    float* dinv = An + 900;             // 30
    float* Ys   = An + 960;             // 3840
    float* Hs   = Ys + 3840;            // 3840
    float* rrow = Hs + 3840;            // 512
    float* xsb  = rrow + 512;           // 30     total 9182 floats = 36728 B

    const float* g = graph + (size_t)b * (BANDS * NN * NN);
    for (int p = tid; p < NN * NN; p += 256) {
        int n = p / NN, m = p - n * NN;
        float s5 = g[p] + g[900 + p] + g[1800 + p] + g[2700 + p] + g[3600 + p];
        float a = (s5 * 0.2f != 0.0f) ? 1.0f : 0.0f;
        if (n == m) a = 1.0f;
        An[p] = a;
    }
    __syncthreads();
    if (tid < NN) {
        float dg = 0.f;
        for (int m = 0; m < NN; m++) dg += An[tid * NN + m];
        dinv[tid] = (dg > 0.f) ? rsqrtf(dg) : 0.0f;
    }
    __syncthreads();
    for (int p = tid; p < NN * NN; p += 256) {
        int n = p / NN, m = p - n * NN;
        An[p] = dinv[n] * An[p] * dinv[m];
    }
    __syncthreads();

    const float* rb = real + (size_t)b * NN * IN_C;
    for (int n = 0; n < NN; n++) {
        for (int c = tid; c < IN_C; c += 256) rrow[c] = rb[n * IN_C + c];
        __syncthreads();
        if (tid < FF) {
            float accv = 0.f;
            for (int c = 0; c < IN_C; c++) accv += rrow[c] * W1[c * FF + tid];
            Ys[n * FF + tid] = accv;
        }
        __syncthreads();
    }
    if (tid < FF) {
        float bb = b1[tid];
        for (int n = 0; n < NN; n++) {
            float accv = 0.f;
            for (int m = 0; m < NN; m++) accv += An[n * NN + m] * Ys[m * FF + tid];
            Hs[n * FF + tid] = fmaxf(accv + bb, 0.0f);
        }
    }
    __syncthreads();
    if (tid < FF) {
        for (int n = 0; n < NN; n++) {
            float accv = 0.f;
            for (int c = 0; c < FF; c++) accv += Hs[n * FF + c] * W2[c * FF + tid];
            Ys[n * FF + tid] = accv;
        }
    }
    __syncthreads();
    if (tid < FF) {
        float bb = b2[tid];
        for (int n = 0; n < NN; n++) {
            float accv = 0.f;
            for (int m = 0; m < NN; m++) accv += An[n * NN + m] * Ys[m * FF + tid];
            Hs[n * FF + tid] = fmaxf(accv + bb, 0.0f);
        }
    }
    __syncthreads();
    if (tid < NN) {
        float accv = 0.f;
        for (int ff = 0; ff < FF; ff++) accv += Hs[tid * FF + ff] * Wlin[ff];
        xsb[tid] = fmaxf(accv + blin[0], 0.0f);
    }
    __syncthreads();
    if (tid < CC) {
        float accv = bconv[tid];
        for (int n = 0; n < NN; n++) accv += xsb[n] * Wconv[tid * NN + n];
        out[(size_t)b * CC + tid] = accv;
    }
    __syncthreads();
}

// ---------------------------------------------------------------------------
// fused kernel: grid 512, block 256, TB=8 batches/block, 4 blocks/SM.
// Warp w: kh = w>>1 (K quarter within chunk), bh = w&1 (batch half).
// For colsum streaming, warp w owns batch w. Lane: f = 4*lane.
// ---------------------------------------------------------------------------
__global__ void __launch_bounds__(256, 4) fused_gcn(
    const float* __restrict__ real, const float* __restrict__ graph,
    const float* __restrict__ W1, const float* __restrict__ b1,
    const float* __restrict__ W2, const float* __restrict__ b2,
    const float* __restrict__ Wlin, const float* __restrict__ blin,
    const float* __restrict__ Wconv, const float* __restrict__ bconv,
    float* __restrict__ out)
{
    // buf layout (time-multiplexed):
    //   layer-1 pipeline: ubuf0 [128][SB] @ 0 (5120 B), ubuf1 @ 5120 (5120 B)
    //   reductions: red64 [4 kh][4 g][128 f] u64 @ 0    (16384 B)
    //   h1T [128][SB] floats @ 32768                    ( 5120 B)
    //   fallback: 36728 B from 0
    __shared__ __align__(16) char buf[38400];
    __shared__ float xp[8][4];
    __shared__ float xs[TB];
    __shared__ float wsum[CC];
    __shared__ int   flagS[TB];

    float* ub0   = (float*)buf;
    float* ub1   = (float*)(buf + 5120);
    u64t*  red64 = (u64t*)buf;
    float* h1T   = (float*)(buf + 32768);

    const int tid  = threadIdx.x;
    const int b0   = blockIdx.x * TB;
    const int w    = tid >> 5;          // warp 0..7
    const int lane = tid & 31;
    const int f4   = lane * 4;
    const int kh   = w >> 1;            // 0..3
    const int bh   = w & 1;             // 0..1

    if (tid < TB) flagS[tid] = 1;
    if (tid < CC) {
        float a = 0.f;
        #pragma unroll
        for (int n = 0; n < NN; n++) a += Wconv[tid * NN + n];
        wsum[tid] = a;
    }
    __syncthreads();

    // ---- graph density flags (coalesced float4, 5 bands summed)
    for (int i = tid; i < TB * 225; i += 256) {
        int b = i / 225, idx = i - b * 225;
        const float4* g4 = (const float4*)(graph + (size_t)(b0 + b) * (BANDS * NN * NN));
        float4 a0 = g4[idx];
        float4 a1 = g4[225 + idx];
        float4 a2 = g4[450 + idx];
        float4 a3 = g4[675 + idx];
        float4 a4 = g4[900 + idx];
        float s[4];
        s[0] = a0.x + a1.x + a2.x + a3.x + a4.x;
        s[1] = a0.y + a1.y + a2.y + a3.y + a4.y;
        s[2] = a0.z + a1.z + a2.z + a3.z + a4.z;
        s[3] = a0.w + a1.w + a2.w + a3.w + a4.w;
        bool bad = false;
        #pragma unroll
        for (int j = 0; j < 4; j++) {
            int p = idx * 4 + j;
            int n = p / NN, m = p - n * NN;
            if (n != m && s[j] * 0.2f == 0.0f) bad = true;
        }
        if (bad) flagS[b] = 0;
    }

    // ---- layer-1 pipeline over 4 K-chunks of 128.
    // Warp w streams colsums of batch w; FMA role: (kh, bh).
    const float4* rb4 = (const float4*)(real + (size_t)(b0 + w) * NN * IN_C);

    // prologue: colsum of chunk 0 -> ub0
    {
        float4 a = make_float4(0.f, 0.f, 0.f, 0.f);
        #pragma unroll 6
        for (int n = 0; n < NN; n++) {
            float4 v = rb4[n * (IN_C / 4) + lane];
            a.x += v.x; a.y += v.y; a.z += v.z; a.w += v.w;
        }
        int kb = lane * 4;
        ub0[(kb + 0) * SB + w] = a.x;
        ub0[(kb + 1) * SB + w] = a.y;
        ub0[(kb + 2) * SB + w] = a.z;
        ub0[(kb + 3) * SB + w] = a.w;
    }
    __syncthreads();

    u64t acc[2][4];
    #pragma unroll
    for (int p = 0; p < 2; p++)
        #pragma unroll
        for (int j = 0; j < 4; j++) acc[p][j] = 0ull;

    for (int c = 0; c < 4; c++) {
        float* ub = (c & 1) ? ub1 : ub0;
        float* un = (c & 1) ? ub0 : ub1;
        const bool more = (c < 3);
        float4 a = make_float4(0.f, 0.f, 0.f, 0.f);
        const int kbeg = kh * 32;                         // within chunk
        const float4* Wp = (const float4*)(W1 + (size_t)(c * 128 + kbeg) * FF) + lane;
        float4 wpf[2];
        wpf[0] = Wp[0];
        wpf[1] = Wp[FF / 4];
        #pragma unroll
        for (int ki = 0; ki < 32; ki++) {
            // stream one colsum row for chunk c+1 (lane = its float4 column)
            float4 v;
            bool ld = more && (ki < NN);
            if (ld) v = rb4[ki * (IN_C / 4) + (c + 1) * 32 + lane];
            float4 wv = wpf[ki & 1];
            if (ki + 2 < 32) wpf[ki & 1] = Wp[(ki + 2) * (FF / 4)];
            const float* up = &ub[(kbeg + ki) * SB + bh * 4];
            u64t u0 = *(const u64t*)(up + 0);
            u64t u1 = *(const u64t*)(up + 2);
            u64t w0 = pk2(wv.x, wv.x), w1 = pk2(wv.y, wv.y);
            u64t w2 = pk2(wv.z, wv.z), w3 = pk2(wv.w, wv.w);
            fma2(acc[0][0], u0, w0); fma2(acc[1][0], u1, w0);
            fma2(acc[0][1], u0, w1); fma2(acc[1][1], u1, w1);
            fma2(acc[0][2], u0, w2); fma2(acc[1][2], u1, w2);
            fma2(acc[0][3], u0, w3); fma2(acc[1][3], u1, w3);
            if (ld) { a.x += v.x; a.y += v.y; a.z += v.z; a.w += v.w; }
        }
        __syncthreads();          // ub reads done; un's previous readers done
        if (more) {
            int kb = lane * 4;
            un[(kb + 0) * SB + w] = a.x;
            un[(kb + 1) * SB + w] = a.y;
            un[(kb + 2) * SB + w] = a.z;
            un[(kb + 3) * SB + w] = a.w;
        }
        __syncthreads();          // un visible for next iteration
    }

    // ---- stash layer-1 partials (red64 aliases the dead ubuf region)
    #pragma unroll
    for (int p = 0; p < 2; p++)
        #pragma unroll
        for (int j = 0; j < 4; j++)
            red64[kh * 512 + (bh * 2 + p) * 128 + f4 + j] = acc[p][j];
    __syncthreads();

    // ---- reduce kh -> h1T. Thread t: f = t&127, gg = t>>7; g = gg, gg+2.
    {
        const float s1 = 1.0f / 30.0f;
        int fr = tid & 127, gg = tid >> 7;
        float bb = b1[fr];
        #pragma unroll
        for (int pi = 0; pi < 2; pi++) {
            int g = gg + 2 * pi;
            float lo = 0.f, hi = 0.f;
            #pragma unroll
            for (int q = 0; q < 4; q++) {
                float av, bv; upk2(av, bv, red64[q * 512 + g * 128 + fr]);
                lo += av; hi += bv;
            }
            h1T[fr * SB + 2 * g]     = fmaxf(fmaf(s1, lo, bb), 0.0f);
            h1T[fr * SB + 2 * g + 1] = fmaxf(fmaf(s1, hi, bb), 0.0f);
        }
    }
    __syncthreads();

    // ---- layer-2 partials. Warp: k in [kh*32, kh*32+32).
    #pragma unroll
    for (int p = 0; p < 2; p++)
        #pragma unroll
        for (int j = 0; j < 4; j++) acc[p][j] = 0ull;
    {
        const int kbeg = kh * 32;
        const float4* Wp = (const float4*)(W2 + (size_t)kbeg * FF) + lane;
        float4 wpf[2];
        wpf[0] = Wp[0];
        wpf[1] = Wp[FF / 4];
        #pragma unroll 4
        for (int ki = 0; ki < 32; ki++) {
            float4 wv = wpf[ki & 1];
            int kn = (ki + 2 < 32) ? (ki + 2) : ki;
            wpf[ki & 1] = Wp[kn * (FF / 4)];
            const float* up = &h1T[(kbeg + ki) * SB + bh * 4];
            u64t u0 = *(const u64t*)(up + 0);
            u64t u1 = *(const u64t*)(up + 2);
            u64t w0 = pk2(wv.x, wv.x), w1 = pk2(wv.y, wv.y);
            u64t w2 = pk2(wv.z, wv.z), w3 = pk2(wv.w, wv.w);
            fma2(acc[0][0], u0, w0); fma2(acc[1][0], u1, w0);
            fma2(acc[0][1], u0, w1); fma2(acc[1][1], u1, w1);
            fma2(acc[0][2], u0, w2); fma2(acc[1][2], u1, w2);
            fma2(acc[0][3], u0, w3); fma2(acc[1][3], u1, w3);
        }
    }
    __syncthreads();   // h1T reads done (red64 write below doesn't touch h1T)
    #pragma unroll
    for (int p = 0; p < 2; p++)
        #pragma unroll
        for (int j = 0; j < 4; j++)
            red64[kh * 512 + (bh * 2 + p) * 128 + f4 + j] = acc[p][j];
    __syncthreads();

    // ---- final reduce + epilogue. Thread t: f = t&127, gg = t>>7.
    {
        int fr = tid & 127, gg = tid >> 7;
        float bb = b2[fr];
        float wl = Wlin[fr];
        float part[4];                     // {g=gg: lo,hi ; g=gg+2: lo,hi}
        #pragma unroll
        for (int pi = 0; pi < 2; pi++) {
            int g = gg + 2 * pi;
            float lo = 0.f, hi = 0.f;
            #pragma unroll
            for (int q = 0; q < 4; q++) {
                float av, bv; upk2(av, bv, red64[q * 512 + g * 128 + fr]);
                lo += av; hi += bv;
            }
            part[2 * pi]     = fmaxf(lo + bb, 0.0f) * wl;
            part[2 * pi + 1] = fmaxf(hi + bb, 0.0f) * wl;
        }
        #pragma unroll
        for (int off = 16; off > 0; off >>= 1)
            #pragma unroll
            for (int cc = 0; cc < 4; cc++)
                part[cc] += __shfl_xor_sync(0xffffffffu, part[cc], off);
        if (lane == 0) {
            xp[w][0] = part[0]; xp[w][1] = part[1];
            xp[w][2] = part[2]; xp[w][3] = part[3];
        }
    }
    __syncthreads();
    if (tid < TB) {
        int b = tid;
        int g  = b >> 1;
        int gg = g & 1;                    // warps gg*4..gg*4+3 hold this g
        int slot = (g >> 1) * 2 + (b & 1);
        float s = xp[gg * 4 + 0][slot] + xp[gg * 4 + 1][slot]
                + xp[gg * 4 + 2][slot] + xp[gg * 4 + 3][slot];
        xs[b] = fmaxf(s + blin[0], 0.0f);
    }
    __syncthreads();

    if (tid < TB * CC) {
        int b = tid / CC, c = tid - b * CC;
        if (flagS[b])
            out[(size_t)(b0 + b) * CC + c] = xs[b] * wsum[c] + bconv[c];
    }
    __syncthreads();

    // ---- honest fallback for any non-dense batch (uniform branch)
    for (int fb = 0; fb < TB; fb++) {
        if (!flagS[fb]) {
            fallback_batch(b0 + fb, buf, tid, real, graph, W1, b1, W2, b2,
                           Wlin, blin, Wconv, bconv, out);
        }
    }
}

// ---------------------------------------------------------------------------
extern "C" void kernel_launch(void* const* d_in, const int* in_sizes, int n_in,
                              void* d_out, int out_size)
{
    const float* real  = (const float*)d_in[0];
    const float* graph = (const float*)d_in[2];
    const float* W1    = (const float*)d_in[3];
    const float* b1    = (const float*)d_in[4];
    const float* W2    = (const float*)d_in[5];
    const float* b2    = (const float*)d_in[6];
    const float* Wlin  = (const float*)d_in[7];
    const float* blin  = (const float*)d_in[8];
    const float* Wconv = (const float*)d_in[9];
    const float* bconv = (const float*)d_in[10];
    float* out = (float*)d_out;

    fused_gcn<<<B_TOT / TB, 256>>>(real, graph, W1, b1, W2, b2, Wlin, blin,
                                   Wconv, bconv, out);
}

// round 9
// speedup vs baseline: 1.8627x; 1.0244x over previous
#include <cuda_runtime.h>
#include <cstdint>

// ---------------------------------------------------------------------------
// GCNNet fused single-kernel implementation.
// An = D^-1/2 (A+I) D^-1/2, A = (mean_bands(graph) != 0). Dense pattern
// (measure-1 for Gaussian graph) => An = (1/30)*J (rank-1):
//   h1 = relu((1/30) colsum(real) @ W1 + b1)      (all rows identical)
//   h2 = relu(h1 @ W2 + b2)                       (An row-sums == 1)
//   x  = relu(h2 . Wlin + blin); out[c] = x * rowsum(Wconv[c]) + bconv[c]
// K processed in 4 chunks of 128, double-buffered colsums; streamed real
// loads use a depth-4 register ring (MLP=4) so DRAM latency is hidden by
// the FFMA2 work of the current chunk.
// ---------------------------------------------------------------------------

#define B_TOT   4096
#define BANDS   5
#define NN      30
#define IN_C    512
#define FF      128
#define CC      9
#define TB      8             // batches per block
#define SB      10            // padded batch stride (floats) in k-major smem

typedef unsigned long long u64t;

// ---- f32x2 helpers --------------------------------------------------------
__device__ __forceinline__ u64t pk2(float lo, float hi) {
    u64t r; asm("mov.b64 %0,{%1,%2};" : "=l"(r) : "f"(lo), "f"(hi)); return r;
}
__device__ __forceinline__ void upk2(float& lo, float& hi, u64t v) {
    asm("mov.b64 {%0,%1},%2;" : "=f"(lo), "=f"(hi) : "l"(v));
}
__device__ __forceinline__ void fma2(u64t& d, u64t a, u64t b) {
    asm("fma.rn.f32x2 %0,%1,%2,%0;" : "+l"(d) : "l"(a), "l"(b));
}

// ---------------------------------------------------------------------------
// honest fallback for one non-dense batch; whole block (256 thr), smem 'buf'
// (>= 36728 bytes) is reused.
// ---------------------------------------------------------------------------
__device__ void fallback_batch(
    int b, char* buf, int tid,
    const float* __restrict__ real, const float* __restrict__ graph,
    const float* __restrict__ W1, const float* __restrict__ b1,
    const float* __restrict__ W2, const float* __restrict__ b2,
    const float* __restrict__ Wlin, const float* __restrict__ blin,
    const float* __restrict__ Wconv, const float* __restrict__ bconv,
    float* __restrict__ out)
{
    float* An   = (float*)buf;          // 900 (pad to 960 incl. dinv)
    float* dinv = An + 900;             // 30
    float* Ys   = An + 960;             // 3840
    float* Hs   = Ys + 3840;            // 3840
    float* rrow = Hs + 3840;            // 512
    float* xsb  = rrow + 512;           // 30     total 9182 floats = 36728 B

    const float* g = graph + (size_t)b * (BANDS * NN * NN);
    for (int p = tid; p < NN * NN; p += 256) {
        int n = p / NN, m = p - n * NN;
        float s5 = g[p] + g[900 + p] + g[1800 + p] + g[2700 + p] + g[3600 + p];
        float a = (s5 * 0.2f != 0.0f) ? 1.0f : 0.0f;
        if (n == m) a = 1.0f;
        An[p] = a;
    }
    __syncthreads();
    if (tid < NN) {
        float dg = 0.f;
        for (int m = 0; m < NN; m++) dg += An[tid * NN + m];
        dinv[tid] = (dg > 0.f) ? rsqrtf(dg) : 0.0f;
    }
    __syncthreads();
    for (int p = tid; p < NN * NN; p += 256) {
        int n = p / NN, m = p - n * NN;
        An[p] = dinv[n] * An[p] * dinv[m];
    }
    __syncthreads();

    const float* rb = real + (size_t)b * NN * IN_C;
    for (int n = 0; n < NN; n++) {
        for (int c = tid; c < IN_C; c += 256) rrow[c] = rb[n * IN_C + c];
        __syncthreads();
        if (tid < FF) {
            float accv = 0.f;
            for (int c = 0; c < IN_C; c++) accv += rrow[c] * W1[c * FF + tid];
            Ys[n * FF + tid] = accv;
        }
        __syncthreads();
    }
    if (tid < FF) {
        float bb = b1[tid];
        for (int n = 0; n < NN; n++) {
            float accv = 0.f;
            for (int m = 0; m < NN; m++) accv += An[n * NN + m] * Ys[m * FF + tid];
            Hs[n * FF + tid] = fmaxf(accv + bb, 0.0f);
        }
    }
    __syncthreads();
    if (tid < FF) {
        for (int n = 0; n < NN; n++) {
            float accv = 0.f;
            for (int c = 0; c < FF; c++) accv += Hs[n * FF + c] * W2[c * FF + tid];
            Ys[n * FF + tid] = accv;
        }
    }
    __syncthreads();
    if (tid < FF) {
        float bb = b2[tid];
        for (int n = 0; n < NN; n++) {
            float accv = 0.f;
            for (int m = 0; m < NN; m++) accv += An[n * NN + m] * Ys[m * FF + tid];
            Hs[n * FF + tid] = fmaxf(accv + bb, 0.0f);
        }
    }
    __syncthreads();
    if (tid < NN) {
        float accv = 0.f;
        for (int ff = 0; ff < FF; ff++) accv += Hs[tid * FF + ff] * Wlin[ff];
        xsb[tid] = fmaxf(accv + blin[0], 0.0f);
    }
    __syncthreads();
    if (tid < CC) {
        float accv = bconv[tid];
        for (int n = 0; n < NN; n++) accv += xsb[n] * Wconv[tid * NN + n];
        out[(size_t)b * CC + tid] = accv;
    }
    __syncthreads();
}

// ---------------------------------------------------------------------------
// fused kernel: grid 512, block 256, TB=8 batches/block, 4 blocks/SM.
// Warp w: kh = w>>1 (K quarter within chunk), bh = w&1 (batch half).
// For colsum streaming, warp w owns batch w. Lane: f = 4*lane.
// ---------------------------------------------------------------------------
__global__ void __launch_bounds__(256, 4) fused_gcn(
    const float* __restrict__ real, const float* __restrict__ graph,
    const float* __restrict__ W1, const float* __restrict__ b1,
    const float* __restrict__ W2, const float* __restrict__ b2,
    const float* __restrict__ Wlin, const float* __restrict__ blin,
    const float* __restrict__ Wconv, const float* __restrict__ bconv,
    float* __restrict__ out)
{
    // buf layout (time-multiplexed):
    //   layer-1 pipeline: ubuf0 [128][SB] @ 0 (5120 B), ubuf1 @ 5120 (5120 B)
    //   reductions: red64 [4 kh][4 g][128 f] u64 @ 0    (16384 B)
    //   h1T [128][SB] floats @ 32768                    ( 5120 B)
    //   fallback: 36728 B from 0
    __shared__ __align__(16) char buf[38400];
    __shared__ float xp[8][4];
    __shared__ float xs[TB];
    __shared__ float wsum[CC];
    __shared__ int   flagS[TB];

    float* ub0   = (float*)buf;
    float* ub1   = (float*)(buf + 5120);
    u64t*  red64 = (u64t*)buf;
    float* h1T   = (float*)(buf + 32768);

    const int tid  = threadIdx.x;
    const int b0   = blockIdx.x * TB;
    const int w    = tid >> 5;          // warp 0..7
    const int lane = tid & 31;
    const int f4   = lane * 4;
    const int kh   = w >> 1;            // 0..3
    const int bh   = w & 1;             // 0..1

    if (tid < TB) flagS[tid] = 1;
    if (tid < CC) {
        float a = 0.f;
        #pragma unroll
        for (int n = 0; n < NN; n++) a += Wconv[tid * NN + n];
        wsum[tid] = a;
    }
    __syncthreads();

    // ---- graph density flags (coalesced float4, 5 bands summed)
    for (int i = tid; i < TB * 225; i += 256) {
        int b = i / 225, idx = i - b * 225;
        const float4* g4 = (const float4*)(graph + (size_t)(b0 + b) * (BANDS * NN * NN));
        float4 a0 = g4[idx];
        float4 a1 = g4[225 + idx];
        float4 a2 = g4[450 + idx];
        float4 a3 = g4[675 + idx];
        float4 a4 = g4[900 + idx];
        float s[4];
        s[0] = a0.x + a1.x + a2.x + a3.x + a4.x;
        s[1] = a0.y + a1.y + a2.y + a3.y + a4.y;
        s[2] = a0.z + a1.z + a2.z + a3.z + a4.z;
        s[3] = a0.w + a1.w + a2.w + a3.w + a4.w;
        bool bad = false;
        #pragma unroll
        for (int j = 0; j < 4; j++) {
            int p = idx * 4 + j;
            int n = p / NN, m = p - n * NN;
            if (n != m && s[j] * 0.2f == 0.0f) bad = true;
        }
        if (bad) flagS[b] = 0;
    }

    // ---- layer-1 pipeline over 4 K-chunks of 128.
    // Warp w streams colsums of batch w; FMA role: (kh, bh).
    const float4* rb4 = (const float4*)(real + (size_t)(b0 + w) * NN * IN_C);

    // prologue: colsum of chunk 0 -> ub0
    {
        float4 a = make_float4(0.f, 0.f, 0.f, 0.f);
        #pragma unroll 6
        for (int n = 0; n < NN; n++) {
            float4 v = rb4[n * (IN_C / 4) + lane];
            a.x += v.x; a.y += v.y; a.z += v.z; a.w += v.w;
        }
        int kb = lane * 4;
        ub0[(kb + 0) * SB + w] = a.x;
        ub0[(kb + 1) * SB + w] = a.y;
        ub0[(kb + 2) * SB + w] = a.z;
        ub0[(kb + 3) * SB + w] = a.w;
    }
    __syncthreads();

    u64t acc[2][4];
    #pragma unroll
    for (int p = 0; p < 2; p++)
        #pragma unroll
        for (int j = 0; j < 4; j++) acc[p][j] = 0ull;

    for (int c = 0; c < 4; c++) {
        float* ub = (c & 1) ? ub1 : ub0;
        float* un = (c & 1) ? ub0 : ub1;
        const bool more = (c < 3);
        const float4* nxt = rb4 + (c + 1) * 32 + lane;    // rows of next chunk
        float4 a = make_float4(0.f, 0.f, 0.f, 0.f);
        const int kbeg = kh * 32;                         // within chunk
        const float4* Wp = (const float4*)(W1 + (size_t)(c * 128 + kbeg) * FF) + lane;
        float4 wpf[2];
        wpf[0] = Wp[0];
        wpf[1] = Wp[FF / 4];

        // depth-4 ring on streamed loads: slot ki&3 holds row ki.
        float4 vr[4];
        if (more) {
            #pragma unroll
            for (int s = 0; s < 4; s++) vr[s] = nxt[s * (IN_C / 4)];
        }
        #pragma unroll
        for (int ki = 0; ki < 32; ki++) {
            float4 v;
            bool cons = more && (ki < NN);
            if (cons) v = vr[ki & 3];                     // row ki (loaded ki-4)
            if (more && (ki + 4 < NN))
                vr[ki & 3] = nxt[(ki + 4) * (IN_C / 4)];  // refill slot: row ki+4
            float4 wv = wpf[ki & 1];
            if (ki + 2 < 32) wpf[ki & 1] = Wp[(ki + 2) * (FF / 4)];
            const float* up = &ub[(kbeg + ki) * SB + bh * 4];
            u64t u0 = *(const u64t*)(up + 0);
            u64t u1 = *(const u64t*)(up + 2);
            u64t w0 = pk2(wv.x, wv.x), w1 = pk2(wv.y, wv.y);
            u64t w2 = pk2(wv.z, wv.z), w3 = pk2(wv.w, wv.w);
            fma2(acc[0][0], u0, w0); fma2(acc[1][0], u1, w0);
            fma2(acc[0][1], u0, w1); fma2(acc[1][1], u1, w1);
            fma2(acc[0][2], u0, w2); fma2(acc[1][2], u1, w2);
            fma2(acc[0][3], u0, w3); fma2(acc[1][3], u1, w3);
            if (cons) { a.x += v.x; a.y += v.y; a.z += v.z; a.w += v.w; }
        }
        __syncthreads();          // ub reads done; un's previous readers done
        if (more) {
            int kb = lane * 4;
            un[(kb + 0) * SB + w] = a.x;
            un[(kb + 1) * SB + w] = a.y;
            un[(kb + 2) * SB + w] = a.z;
            un[(kb + 3) * SB + w] = a.w;
        }
        __syncthreads();          // un visible for next iteration
    }

    // ---- stash layer-1 partials (red64 aliases the dead ubuf region)
    #pragma unroll
    for (int p = 0; p < 2; p++)
        #pragma unroll
        for (int j = 0; j < 4; j++)
            red64[kh * 512 + (bh * 2 + p) * 128 + f4 + j] = acc[p][j];
    __syncthreads();

    // ---- reduce kh -> h1T. Thread t: f = t&127, gg = t>>7; g = gg, gg+2.
    {
        const float s1 = 1.0f / 30.0f;
        int fr = tid & 127, gg = tid >> 7;
        float bb = b1[fr];
        #pragma unroll
        for (int pi = 0; pi < 2; pi++) {
            int g = gg + 2 * pi;
            float lo = 0.f, hi = 0.f;
            #pragma unroll
            for (int q = 0; q < 4; q++) {
                float av, bv; upk2(av, bv, red64[q * 512 + g * 128 + fr]);
                lo += av; hi += bv;
            }
            h1T[fr * SB + 2 * g]     = fmaxf(fmaf(s1, lo, bb), 0.0f);
            h1T[fr * SB + 2 * g + 1] = fmaxf(fmaf(s1, hi, bb), 0.0f);
        }
    }
    __syncthreads();

    // ---- layer-2 partials. Warp: k in [kh*32, kh*32+32).
    #pragma unroll
    for (int p = 0; p < 2; p++)
        #pragma unroll
        for (int j = 0; j < 4; j++) acc[p][j] = 0ull;
    {
        const int kbeg = kh * 32;
        const float4* Wp = (const float4*)(W2 + (size_t)kbeg * FF) + lane;
        float4 wpf[2];
        wpf[0] = Wp[0];
        wpf[1] = Wp[FF / 4];
        #pragma unroll 4
        for (int ki = 0; ki < 32; ki++) {
            float4 wv = wpf[ki & 1];
            int kn = (ki + 2 < 32) ? (ki + 2) : ki;
            wpf[ki & 1] = Wp[kn * (FF / 4)];
            const float* up = &h1T[(kbeg + ki) * SB + bh * 4];
            u64t u0 = *(const u64t*)(up + 0);
            u64t u1 = *(const u64t*)(up + 2);
            u64t w0 = pk2(wv.x, wv.x), w1 = pk2(wv.y, wv.y);
            u64t w2 = pk2(wv.z, wv.z), w3 = pk2(wv.w, wv.w);
            fma2(acc[0][0], u0, w0); fma2(acc[1][0], u1, w0);
            fma2(acc[0][1], u0, w1); fma2(acc[1][1], u1, w1);
            fma2(acc[0][2], u0, w2); fma2(acc[1][2], u1, w2);
            fma2(acc[0][3], u0, w3); fma2(acc[1][3], u1, w3);
        }
    }
    __syncthreads();   // h1T reads done (red64 write below doesn't touch h1T)
    #pragma unroll
    for (int p = 0; p < 2; p++)
        #pragma unroll
        for (int j = 0; j < 4; j++)
            red64[kh * 512 + (bh * 2 + p) * 128 + f4 + j] = acc[p][j];
    __syncthreads();

    // ---- final reduce + epilogue. Thread t: f = t&127, gg = t>>7.
    {
        int fr = tid & 127, gg = tid >> 7;
        float bb = b2[fr];
        float wl = Wlin[fr];
        float part[4];                     // {g=gg: lo,hi ; g=gg+2: lo,hi}
        #pragma unroll
        for (int pi = 0; pi < 2; pi++) {
            int g = gg + 2 * pi;
            float lo = 0.f, hi = 0.f;
            #pragma unroll
            for (int q = 0; q < 4; q++) {
                float av, bv; upk2(av, bv, red64[q * 512 + g * 128 + fr]);
                lo += av; hi += bv;
            }
            part[2 * pi]     = fmaxf(lo + bb, 0.0f) * wl;
            part[2 * pi + 1] = fmaxf(hi + bb, 0.0f) * wl;
        }
        #pragma unroll
        for (int off = 16; off > 0; off >>= 1)
            #pragma unroll
            for (int cc = 0; cc < 4; cc++)
                part[cc] += __shfl_xor_sync(0xffffffffu, part[cc], off);
        if (lane == 0) {
            xp[w][0] = part[0]; xp[w][1] = part[1];
            xp[w][2] = part[2]; xp[w][3] = part[3];
        }
    }
    __syncthreads();
    if (tid < TB) {
        int b = tid;
        int g  = b >> 1;
        int gg = g & 1;                    // warps gg*4..gg*4+3 hold this g
        int slot = (g >> 1) * 2 + (b & 1);
        float s = xp[gg * 4 + 0][slot] + xp[gg * 4 + 1][slot]
                + xp[gg * 4 + 2][slot] + xp[gg * 4 + 3][slot];
        xs[b] = fmaxf(s + blin[0], 0.0f);
    }
    __syncthreads();

    if (tid < TB * CC) {
        int b = tid / CC, c = tid - b * CC;
        if (flagS[b])
            out[(size_t)(b0 + b) * CC + c] = xs[b] * wsum[c] + bconv[c];
    }
    __syncthreads();

    // ---- honest fallback for any non-dense batch (uniform branch)
    for (int fb = 0; fb < TB; fb++) {
        if (!flagS[fb]) {
            fallback_batch(b0 + fb, buf, tid, real, graph, W1, b1, W2, b2,
                           Wlin, blin, Wconv, bconv, out);
        }
    }
}

// ---------------------------------------------------------------------------
extern "C" void kernel_launch(void* const* d_in, const int* in_sizes, int n_in,
                              void* d_out, int out_size)
{
    const float* real  = (const float*)d_in[0];
    const float* graph = (const float*)d_in[2];
    const float* W1    = (const float*)d_in[3];
    const float* b1    = (const float*)d_in[4];
    const float* W2    = (const float*)d_in[5];
    const float* b2    = (const float*)d_in[6];
    const float* Wlin  = (const float*)d_in[7];
    const float* blin  = (const float*)d_in[8];
    const float* Wconv = (const float*)d_in[9];
    const float* bconv = (const float*)d_in[10];
    float* out = (float*)d_out;

    fused_gcn<<<B_TOT / TB, 256>>>(real, graph, W1, b1, W2, b2, Wlin, blin,
                                   Wconv, bconv, out);
}

// round 10
// speedup vs baseline: 1.9131x; 1.0270x over previous
#include <cuda_runtime.h>
#include <cstdint>

// ---------------------------------------------------------------------------
// GCNNet fused single-kernel implementation.
// An = D^-1/2 (A+I) D^-1/2, A = (mean_bands(graph) != 0). Dense pattern
// (measure-1 for Gaussian graph) => An = (1/30)*J (rank-1):
//   h1 = relu((1/30) colsum(real) @ W1 + b1)      (all rows identical)
//   h2 = relu(h1 @ W2 + b2)                       (An row-sums == 1)
//   x  = relu(h2 . Wlin + blin); out[c] = x * rowsum(Wconv[c]) + bconv[c]
// K processed in 4 chunks of 128, double-buffered colsums, depth-4 load ring.
// Block-parity phase staggering: even blocks do the graph-flag streaming
// first, odd blocks do it after layer-2 — so on every SM half the resident
// blocks are in a DRAM phase while the other half are in a compute phase.
// ---------------------------------------------------------------------------

#define B_TOT   4096
#define BANDS   5
#define NN      30
#define IN_C    512
#define FF      128
#define CC      9
#define TB      8             // batches per block
#define SB      10            // padded batch stride (floats) in k-major smem

typedef unsigned long long u64t;

// ---- f32x2 helpers --------------------------------------------------------
__device__ __forceinline__ u64t pk2(float lo, float hi) {
    u64t r; asm("mov.b64 %0,{%1,%2};" : "=l"(r) : "f"(lo), "f"(hi)); return r;
}
__device__ __forceinline__ void upk2(float& lo, float& hi, u64t v) {
    asm("mov.b64 {%0,%1},%2;" : "=f"(lo), "=f"(hi) : "l"(v));
}
__device__ __forceinline__ void fma2(u64t& d, u64t a, u64t b) {
    asm("fma.rn.f32x2 %0,%1,%2,%0;" : "+l"(d) : "l"(a), "l"(b));
}

// ---------------------------------------------------------------------------
// graph density flags for TB batches (writes flagS[b]=0 on any zero mean).
// ---------------------------------------------------------------------------
__device__ __forceinline__ void flags_check(
    int b0, int tid, const float* __restrict__ graph, int* flagS)
{
    for (int i = tid; i < TB * 225; i += 256) {
        int b = i / 225, idx = i - b * 225;
        const float4* g4 = (const float4*)(graph + (size_t)(b0 + b) * (BANDS * NN * NN));
        float4 a0 = g4[idx];
        float4 a1 = g4[225 + idx];
        float4 a2 = g4[450 + idx];
        float4 a3 = g4[675 + idx];
        float4 a4 = g4[900 + idx];
        float s[4];
        s[0] = a0.x + a1.x + a2.x + a3.x + a4.x;
        s[1] = a0.y + a1.y + a2.y + a3.y + a4.y;
        s[2] = a0.z + a1.z + a2.z + a3.z + a4.z;
        s[3] = a0.w + a1.w + a2.w + a3.w + a4.w;
        bool bad = false;
        #pragma unroll
        for (int j = 0; j < 4; j++) {
            int p = idx * 4 + j;
            int n = p / NN, m = p - n * NN;
            if (n != m && s[j] * 0.2f == 0.0f) bad = true;
        }
        if (bad) flagS[b] = 0;
    }
}

// ---------------------------------------------------------------------------
// honest fallback for one non-dense batch; whole block (256 thr), smem 'buf'
// (>= 36728 bytes) is reused.
// ---------------------------------------------------------------------------
__device__ void fallback_batch(
    int b, char* buf, int tid,
    const float* __restrict__ real, const float* __restrict__ graph,
    const float* __restrict__ W1, const float* __restrict__ b1,
    const float* __restrict__ W2, const float* __restrict__ b2,
    const float* __restrict__ Wlin, const float* __restrict__ blin,
    const float* __restrict__ Wconv, const float* __restrict__ bconv,
    float* __restrict__ out)
{
    float* An   = (float*)buf;          // 900 (pad to 960 incl. dinv)
    float* dinv = An + 900;             // 30
    float* Ys   = An + 960;             // 3840
    float* Hs   = Ys + 3840;            // 3840
    float* rrow = Hs + 3840;            // 512
    float* xsb  = rrow + 512;           // 30     total 9182 floats = 36728 B

    const float* g = graph + (size_t)b * (BANDS * NN * NN);
    for (int p = tid; p < NN * NN; p += 256) {
        int n = p / NN, m = p - n * NN;
        float s5 = g[p] + g[900 + p] + g[1800 + p] + g[2700 + p] + g[3600 + p];
        float a = (s5 * 0.2f != 0.0f) ? 1.0f : 0.0f;
        if (n == m) a = 1.0f;
        An[p] = a;
    }
    __syncthreads();
    if (tid < NN) {
        float dg = 0.f;
        for (int m = 0; m < NN; m++) dg += An[tid * NN + m];
        dinv[tid] = (dg > 0.f) ? rsqrtf(dg) : 0.0f;
    }
    __syncthreads();
    for (int p = tid; p < NN * NN; p += 256) {
        int n = p / NN, m = p - n * NN;
        An[p] = dinv[n] * An[p] * dinv[m];
    }
    __syncthreads();

    const float* rb = real + (size_t)b * NN * IN_C;
    for (int n = 0; n < NN; n++) {
        for (int c = tid; c < IN_C; c += 256) rrow[c] = rb[n * IN_C + c];
        __syncthreads();
        if (tid < FF) {
            float accv = 0.f;
            for (int c = 0; c < IN_C; c++) accv += rrow[c] * W1[c * FF + tid];
            Ys[n * FF + tid] = accv;
        }
        __syncthreads();
    }
    if (tid < FF) {
        float bb = b1[tid];
        for (int n = 0; n < NN; n++) {
            float accv = 0.f;
            for (int m = 0; m < NN; m++) accv += An[n * NN + m] * Ys[m * FF + tid];
            Hs[n * FF + tid] = fmaxf(accv + bb, 0.0f);
        }
    }
    __syncthreads();
    if (tid < FF) {
        for (int n = 0; n < NN; n++) {
            float accv = 0.f;
            for (int c = 0; c < FF; c++) accv += Hs[n * FF + c] * W2[c * FF + tid];
            Ys[n * FF + tid] = accv;
        }
    }
    __syncthreads();
    if (tid < FF) {
        float bb = b2[tid];
        for (int n = 0; n < NN; n++) {
            float accv = 0.f;
            for (int m = 0; m < NN; m++) accv += An[n * NN + m] * Ys[m * FF + tid];
            Hs[n * FF + tid] = fmaxf(accv + bb, 0.0f);
        }
    }
    __syncthreads();
    if (tid < NN) {
        float accv = 0.f;
        for (int ff = 0; ff < FF; ff++) accv += Hs[tid * FF + ff] * Wlin[ff];
        xsb[tid] = fmaxf(accv + blin[0], 0.0f);
    }
    __syncthreads();
    if (tid < CC) {
        float accv = bconv[tid];
        for (int n = 0; n < NN; n++) accv += xsb[n] * Wconv[tid * NN + n];
        out[(size_t)b * CC + tid] = accv;
    }
    __syncthreads();
}

// ---------------------------------------------------------------------------
// fused kernel: grid 512, block 256, TB=8 batches/block, 4 blocks/SM.
// Warp w: kh = w>>1 (K quarter within chunk), bh = w&1 (batch half).
// For colsum streaming, warp w owns batch w. Lane: f = 4*lane.
// ---------------------------------------------------------------------------
__global__ void __launch_bounds__(256, 4) fused_gcn(
    const float* __restrict__ real, const float* __restrict__ graph,
    const float* __restrict__ W1, const float* __restrict__ b1,
    const float* __restrict__ W2, const float* __restrict__ b2,
    const float* __restrict__ Wlin, const float* __restrict__ blin,
    const float* __restrict__ Wconv, const float* __restrict__ bconv,
    float* __restrict__ out)
{
    // buf layout (time-multiplexed):
    //   layer-1 pipeline: ubuf0 [128][SB] @ 0 (5120 B), ubuf1 @ 5120 (5120 B)
    //   reductions: red64 [4 kh][4 g][128 f] u64 @ 0    (16384 B)
    //   h1T [128][SB] floats @ 32768                    ( 5120 B)
    //   fallback: 36728 B from 0
    __shared__ __align__(16) char buf[38400];
    __shared__ float xp[8][4];
    __shared__ float xs[TB];
    __shared__ float wsum[CC];
    __shared__ int   flagS[TB];

    float* ub0   = (float*)buf;
    float* ub1   = (float*)(buf + 5120);
    u64t*  red64 = (u64t*)buf;
    float* h1T   = (float*)(buf + 32768);

    const int tid  = threadIdx.x;
    const int b0   = blockIdx.x * TB;
    const int w    = tid >> 5;          // warp 0..7
    const int lane = tid & 31;
    const int f4   = lane * 4;
    const int kh   = w >> 1;            // 0..3
    const int bh   = w & 1;             // 0..1
    const bool flags_early = ((blockIdx.x & 1) == 0);

    if (tid < TB) flagS[tid] = 1;
    if (tid < CC) {
        float a = 0.f;
        #pragma unroll
        for (int n = 0; n < NN; n++) a += Wconv[tid * NN + n];
        wsum[tid] = a;
    }
    __syncthreads();

    // ---- graph density flags: even blocks now, odd blocks after layer-2
    if (flags_early)
        flags_check(b0, tid, graph, flagS);

    // ---- layer-1 pipeline over 4 K-chunks of 128.
    // Warp w streams colsums of batch w; FMA role: (kh, bh).
    const float4* rb4 = (const float4*)(real + (size_t)(b0 + w) * NN * IN_C);

    // prologue: colsum of chunk 0 -> ub0
    {
        float4 a = make_float4(0.f, 0.f, 0.f, 0.f);
        #pragma unroll 6
        for (int n = 0; n < NN; n++) {
            float4 v = rb4[n * (IN_C / 4) + lane];
            a.x += v.x; a.y += v.y; a.z += v.z; a.w += v.w;
        }
        int kb = lane * 4;
        ub0[(kb + 0) * SB + w] = a.x;
        ub0[(kb + 1) * SB + w] = a.y;
        ub0[(kb + 2) * SB + w] = a.z;
        ub0[(kb + 3) * SB + w] = a.w;
    }
    __syncthreads();

    u64t acc[2][4];
    #pragma unroll
    for (int p = 0; p < 2; p++)
        #pragma unroll
        for (int j = 0; j < 4; j++) acc[p][j] = 0ull;

    for (int c = 0; c < 4; c++) {
        float* ub = (c & 1) ? ub1 : ub0;
        float* un = (c & 1) ? ub0 : ub1;
        const bool more = (c < 3);
        const float4* nxt = rb4 + (c + 1) * 32 + lane;    // rows of next chunk
        float4 a = make_float4(0.f, 0.f, 0.f, 0.f);
        const int kbeg = kh * 32;                         // within chunk
        const float4* Wp = (const float4*)(W1 + (size_t)(c * 128 + kbeg) * FF) + lane;
        float4 wpf[2];
        wpf[0] = Wp[0];
        wpf[1] = Wp[FF / 4];

        // depth-4 ring on streamed loads: slot ki&3 holds row ki.
        float4 vr[4];
        if (more) {
            #pragma unroll
            for (int s = 0; s < 4; s++) vr[s] = nxt[s * (IN_C / 4)];
        }
        #pragma unroll
        for (int ki = 0; ki < 32; ki++) {
            float4 v;
            bool cons = more && (ki < NN);
            if (cons) v = vr[ki & 3];                     // row ki (loaded ki-4)
            if (more && (ki + 4 < NN))
                vr[ki & 3] = nxt[(ki + 4) * (IN_C / 4)];  // refill slot: row ki+4
            float4 wv = wpf[ki & 1];
            if (ki + 2 < 32) wpf[ki & 1] = Wp[(ki + 2) * (FF / 4)];
            const float* up = &ub[(kbeg + ki) * SB + bh * 4];
            u64t u0 = *(const u64t*)(up + 0);
            u64t u1 = *(const u64t*)(up + 2);
            u64t w0 = pk2(wv.x, wv.x), w1 = pk2(wv.y, wv.y);
            u64t w2 = pk2(wv.z, wv.z), w3 = pk2(wv.w, wv.w);
            fma2(acc[0][0], u0, w0); fma2(acc[1][0], u1, w0);
            fma2(acc[0][1], u0, w1); fma2(acc[1][1], u1, w1);
            fma2(acc[0][2], u0, w2); fma2(acc[1][2], u1, w2);
            fma2(acc[0][3], u0, w3); fma2(acc[1][3], u1, w3);
            if (cons) { a.x += v.x; a.y += v.y; a.z += v.z; a.w += v.w; }
        }
        __syncthreads();          // ub reads done; un's previous readers done
        if (more) {
            int kb = lane * 4;
            un[(kb + 0) * SB + w] = a.x;
            un[(kb + 1) * SB + w] = a.y;
            un[(kb + 2) * SB + w] = a.z;
            un[(kb + 3) * SB + w] = a.w;
        }
        __syncthreads();          // un visible for next iteration
    }

    // ---- stash layer-1 partials (red64 aliases the dead ubuf region)
    #pragma unroll
    for (int p = 0; p < 2; p++)
        #pragma unroll
        for (int j = 0; j < 4; j++)
            red64[kh * 512 + (bh * 2 + p) * 128 + f4 + j] = acc[p][j];
    __syncthreads();

    // ---- reduce kh -> h1T. Thread t: f = t&127, gg = t>>7; g = gg, gg+2.
    {
        const float s1 = 1.0f / 30.0f;
        int fr = tid & 127, gg = tid >> 7;
        float bb = b1[fr];
        #pragma unroll
        for (int pi = 0; pi < 2; pi++) {
            int g = gg + 2 * pi;
            float lo = 0.f, hi = 0.f;
            #pragma unroll
            for (int q = 0; q < 4; q++) {
                float av, bv; upk2(av, bv, red64[q * 512 + g * 128 + fr]);
                lo += av; hi += bv;
            }
            h1T[fr * SB + 2 * g]     = fmaxf(fmaf(s1, lo, bb), 0.0f);
            h1T[fr * SB + 2 * g + 1] = fmaxf(fmaf(s1, hi, bb), 0.0f);
        }
    }
    __syncthreads();

    // ---- layer-2 partials. Warp: k in [kh*32, kh*32+32).
    #pragma unroll
    for (int p = 0; p < 2; p++)
        #pragma unroll
        for (int j = 0; j < 4; j++) acc[p][j] = 0ull;
    {
        const int kbeg = kh * 32;
        const float4* Wp = (const float4*)(W2 + (size_t)kbeg * FF) + lane;
        float4 wpf[2];
        wpf[0] = Wp[0];
        wpf[1] = Wp[FF / 4];
        #pragma unroll 4
        for (int ki = 0; ki < 32; ki++) {
            float4 wv = wpf[ki & 1];
            int kn = (ki + 2 < 32) ? (ki + 2) : ki;
            wpf[ki & 1] = Wp[kn * (FF / 4)];
            const float* up = &h1T[(kbeg + ki) * SB + bh * 4];
            u64t u0 = *(const u64t*)(up + 0);
            u64t u1 = *(const u64t*)(up + 2);
            u64t w0 = pk2(wv.x, wv.x), w1 = pk2(wv.y, wv.y);
            u64t w2 = pk2(wv.z, wv.z), w3 = pk2(wv.w, wv.w);
            fma2(acc[0][0], u0, w0); fma2(acc[1][0], u1, w0);
            fma2(acc[0][1], u0, w1); fma2(acc[1][1], u1, w1);
            fma2(acc[0][2], u0, w2); fma2(acc[1][2], u1, w2);
            fma2(acc[0][3], u0, w3); fma2(acc[1][3], u1, w3);
        }
    }
    __syncthreads();   // h1T reads done (red64 write below doesn't touch h1T)
    #pragma unroll
    for (int p = 0; p < 2; p++)
        #pragma unroll
        for (int j = 0; j < 4; j++)
            red64[kh * 512 + (bh * 2 + p) * 128 + f4 + j] = acc[p][j];

    // ---- graph density flags for odd blocks: streams DRAM here, overlapping
    // other blocks' compute tails (and vice versa).
    if (!flags_early)
        flags_check(b0, tid, graph, flagS);
    __syncthreads();

    // ---- final reduce + epilogue. Thread t: f = t&127, gg = t>>7.
    {
        int fr = tid & 127, gg = tid >> 7;
        float bb = b2[fr];
        float wl = Wlin[fr];
        float part[4];                     // {g=gg: lo,hi ; g=gg+2: lo,hi}
        #pragma unroll
        for (int pi = 0; pi < 2; pi++) {
            int g = gg + 2 * pi;
            float lo = 0.f, hi = 0.f;
            #pragma unroll
            for (int q = 0; q < 4; q++) {
                float av, bv; upk2(av, bv, red64[q * 512 + g * 128 + fr]);
                lo += av; hi += bv;
            }
            part[2 * pi]     = fmaxf(lo + bb, 0.0f) * wl;
            part[2 * pi + 1] = fmaxf(hi + bb, 0.0f) * wl;
        }
        #pragma unroll
        for (int off = 16; off > 0; off >>= 1)
            #pragma unroll
            for (int cc = 0; cc < 4; cc++)
                part[cc] += __shfl_xor_sync(0xffffffffu, part[cc], off);
        if (lane == 0) {
            xp[w][0] = part[0]; xp[w][1] = part[1];
            xp[w][2] = part[2]; xp[w][3] = part[3];
        }
    }
    __syncthreads();
    if (tid < TB) {
        int b = tid;
        int g  = b >> 1;
        int gg = g & 1;                    // warps gg*4..gg*4+3 hold this g
        int slot = (g >> 1) * 2 + (b & 1);
        float s = xp[gg * 4 + 0][slot] + xp[gg * 4 + 1][slot]
                + xp[gg * 4 + 2][slot] + xp[gg * 4 + 3][slot];
        xs[b] = fmaxf(s + blin[0], 0.0f);
    }
    __syncthreads();

    if (tid < TB * CC) {
        int b = tid / CC, c = tid - b * CC;
        if (flagS[b])
            out[(size_t)(b0 + b) * CC + c] = xs[b] * wsum[c] + bconv[c];
    }
    __syncthreads();

    // ---- honest fallback for any non-dense batch (uniform branch)
    for (int fb = 0; fb < TB; fb++) {
        if (!flagS[fb]) {
            fallback_batch(b0 + fb, buf, tid, real, graph, W1, b1, W2, b2,
                           Wlin, blin, Wconv, bconv, out);
        }
    }
}

// ---------------------------------------------------------------------------
extern "C" void kernel_launch(void* const* d_in, const int* in_sizes, int n_in,
                              void* d_out, int out_size)
{
    const float* real  = (const float*)d_in[0];
    const float* graph = (const float*)d_in[2];
    const float* W1    = (const float*)d_in[3];
    const float* b1    = (const float*)d_in[4];
    const float* W2    = (const float*)d_in[5];
    const float* b2    = (const float*)d_in[6];
    const float* Wlin  = (const float*)d_in[7];
    const float* blin  = (const float*)d_in[8];
    const float* Wconv = (const float*)d_in[9];
    const float* bconv = (const float*)d_in[10];
    float* out = (float*)d_out;

    fused_gcn<<<B_TOT / TB, 256>>>(real, graph, W1, b1, W2, b2, Wlin, blin,
                                   Wconv, bconv, out);
}